// round 15
// baseline (speedup 1.0000x reference)
#include <cuda_runtime.h>
#include <cuda_fp16.h>
#include <math.h>
#include <stdint.h>

#define H    3072
#define NH   24
#define HD   128
#define MLPD 12288
#define LT   512
#define LI   1024
#define L    1536
#define QKV3 9216
#define MOD6 18432
#define MSPLIT 16
#define MROWS (H / MSPLIT)   // 192

#define ROWB   144
#define ABUF   (128 * ROWB)
#define STAGEB (2 * ABUF)
#define DSMEM  (2 * STAGEB)

// ---------------- scratch ----------------
__device__ float g_mod_img[MOD6];
__device__ float g_mod_txt[MOD6];
__device__ float g_modp[(size_t)2 * MSPLIT * MOD6];
__device__ float g_res2[(size_t)L * H];
__device__ __align__(16) __half g_qkvh[(size_t)L * QKV3];
__device__ __align__(16) __half g_xmod[(size_t)L * H];
__device__ __align__(16) __half g_q   [(size_t)NH * L * HD];
__device__ __align__(16) __half g_k   [(size_t)NH * L * HD];
__device__ __align__(16) __half g_v   [(size_t)NH * HD * L];
__device__ __align__(16) __half g_S   [(size_t)NH * L * L];
__device__ __align__(16) __half g_attn[(size_t)L * H];
__device__ __align__(16) __half g_hbuf[(size_t)L * H];
__device__ __align__(16) __half g_fc1 [(size_t)L * MLPD];
__device__ __align__(16) __half g_qkvw_t [(size_t)QKV3 * H];
__device__ __align__(16) __half g_qkvcw_t[(size_t)QKV3 * H];
__device__ __align__(16) __half g_outw_t [(size_t)H * H];
__device__ __align__(16) __half g_outcw_t[(size_t)H * H];
__device__ __align__(16) __half g_fc1w_t [(size_t)MLPD * H];
__device__ __align__(16) __half g_fc1cw_t[(size_t)MLPD * H];
__device__ __align__(16) __half g_fc2w_t [(size_t)H * MLPD];
__device__ __align__(16) __half g_fc2cw_t[(size_t)H * MLPD];

// ---------------- ptx helpers ----------------
__device__ __forceinline__ uint32_t smem_u32(const void* p) {
    uint32_t a;
    asm("{ .reg .u64 t; cvta.to.shared.u64 t, %1; cvt.u32.u64 %0, t; }" : "=r"(a) : "l"(p));
    return a;
}
__device__ __forceinline__ void cp16(uint32_t dst, const void* src) {
    asm volatile("cp.async.cg.shared.global [%0], [%1], 16;" :: "r"(dst), "l"(src));
}
__device__ __forceinline__ void cp_commit() { asm volatile("cp.async.commit_group;"); }
__device__ __forceinline__ void cp_wait1()  { asm volatile("cp.async.wait_group 1;"); }
__device__ __forceinline__ void ldm4(unsigned* r, uint32_t a) {
    asm volatile("ldmatrix.sync.aligned.m8n8.x4.shared.b16 {%0,%1,%2,%3}, [%4];"
                 : "=r"(r[0]), "=r"(r[1]), "=r"(r[2]), "=r"(r[3]) : "r"(a));
}
__device__ __forceinline__ void mma_f16(float* c, const unsigned* a, const unsigned* b) {
    asm volatile(
        "mma.sync.aligned.m16n8k16.row.col.f32.f16.f16.f32 "
        "{%0,%1,%2,%3}, {%4,%5,%6,%7}, {%8,%9}, {%0,%1,%2,%3};\n"
        : "+f"(c[0]), "+f"(c[1]), "+f"(c[2]), "+f"(c[3])
        : "r"(a[0]), "r"(a[1]), "r"(a[2]), "r"(a[3]), "r"(b[0]), "r"(b[1]));
}
__device__ __forceinline__ float gelu_tanh(float x) {
    return 0.5f * x * (1.f + tanhf(0.7978845608028654f * (x + 0.044715f * x * x * x)));
}

// ---------------- reduce helpers ----------------
__device__ __forceinline__ float block_reduce_sum(float v, float* sh) {
    #pragma unroll
    for (int o = 16; o; o >>= 1) v += __shfl_xor_sync(0xffffffffu, v, o);
    int w = threadIdx.x >> 5;
    if ((threadIdx.x & 31) == 0) sh[w] = v;
    __syncthreads();
    if (threadIdx.x < 32) {
        float x = (threadIdx.x < (blockDim.x >> 5)) ? sh[threadIdx.x] : 0.f;
        #pragma unroll
        for (int o = 16; o; o >>= 1) x += __shfl_xor_sync(0xffffffffu, x, o);
        if (threadIdx.x == 0) sh[0] = x;
    }
    __syncthreads();
    return sh[0];
}
__device__ __forceinline__ float block_reduce_max(float v, float* sh) {
    #pragma unroll
    for (int o = 16; o; o >>= 1) v = fmaxf(v, __shfl_xor_sync(0xffffffffu, v, o));
    int w = threadIdx.x >> 5;
    if ((threadIdx.x & 31) == 0) sh[w] = v;
    __syncthreads();
    if (threadIdx.x < 32) {
        float x = (threadIdx.x < (blockDim.x >> 5)) ? sh[threadIdx.x] : -3.4e38f;
        #pragma unroll
        for (int o = 16; o; o >>= 1) x = fmaxf(x, __shfl_xor_sync(0xffffffffu, x, o));
        if (threadIdx.x == 0) sh[0] = x;
    }
    __syncthreads();
    return sh[0];
}

// ---------------- weight convert+transpose v2: 64k x 64n tiles, paired weights ----------------
__global__ void __launch_bounds__(256) wt2_kernel(const float* __restrict__ w1,
                                                  const float* __restrict__ w2,
                                                  __half* __restrict__ o1,
                                                  __half* __restrict__ o2,
                                                  int K, int N) {
    __shared__ float t[64][65];
    const float* W  = blockIdx.z ? w2 : w1;
    __half*      Wt = blockIdx.z ? o2 : o1;
    const int n0 = blockIdx.x * 64;
    const int k0 = blockIdx.y * 64;
    const int tid = threadIdx.x;
    // read 64k x 64n: 4 float4 per thread, streaming
    #pragma unroll
    for (int r = 0; r < 4; r++) {
        int id = tid + r * 256;
        int k = id >> 4, n4 = (id & 15) * 4;
        float4 v = __ldcs((const float4*)&W[(size_t)(k0 + k) * N + n0 + n4]);
        t[k][n4] = v.x; t[k][n4 + 1] = v.y; t[k][n4 + 2] = v.z; t[k][n4 + 3] = v.w;
    }
    __syncthreads();
    // write: thread (n = tid>>2, kh = (tid&3)*16) -> 16 k halves = 2 uint4, contiguous per 4 threads
    const int n = tid >> 2, kh = (tid & 3) * 16;
    __half hv[16];
    #pragma unroll
    for (int i = 0; i < 16; i++) hv[i] = __float2half(t[kh + i][n]);
    __half* dst = &Wt[(size_t)(n0 + n) * K + k0 + kh];
    *(uint4*)dst       = *(uint4*)hv;
    *(uint4*)(dst + 8) = *(uint4*)(hv + 8);
}

// ================= fp16 NT GEMM: 128x128 block, 4 warps, 64x64 warp tile =================
__global__ void __launch_bounds__(128, 2) hgemm(const __half* __restrict__ A, int lda, long long sA,
                                                const __half* __restrict__ B, const __half* __restrict__ B2,
                                                int ldb, long long sB,
                                                void* __restrict__ Cv, void* __restrict__ Cv2,
                                                int ldc, long long sC, int c_half,
                                                int K, float alpha, int mSplit,
                                                const float* __restrict__ bias, const float* __restrict__ bias2,
                                                const float* __restrict__ gate, const float* __restrict__ gate2,
                                                const float* __restrict__ residual, const float* __restrict__ residual2,
                                                int ldr, int mode) {
    extern __shared__ char smem[];
    const int tid  = threadIdx.x;
    const int warp = tid >> 5, lane = tid & 31;
    const int g = lane >> 2, tg = lane & 3;
    const int bm = blockIdx.x * 128, bn = blockIdx.y * 128;
    const int wm = (warp >> 1) * 64, wn = (warp & 1) * 64;

    const bool second = (int)blockIdx.x >= mSplit;
    const __half* Bp = second ? B2 : B;
    const float* biasp = second ? bias2 : bias;
    const float* gatep = second ? gate2 : gate;
    const float* resp  = second ? residual2 : residual;
    void* Cp = second ? Cv2 : Cv;

    const __half* Ap = A + (long long)blockIdx.z * sA + (long long)bm * lda;
    Bp += (long long)blockIdx.z * sB + (long long)bn * ldb;

    const uint32_t s0 = smem_u32(smem);
    const int cm = tid >> 3, ckh = tid & 7;

    const uint32_t a_off = (uint32_t)((wm + (lane & 7) + ((lane >> 3) & 1) * 8) * ROWB + (lane >> 4) * 16);
    const uint32_t b_off = (uint32_t)((wn + (lane & 7) + ((lane >> 4) & 1) * 8) * ROWB + ((lane >> 3) & 1) * 16);

    const int nch = K >> 6;

    {
        const uint32_t sa = s0, sb = s0 + ABUF;
        #pragma unroll
        for (int r = 0; r < 8; r++) {
            int m = cm + r * 16;
            cp16(sa + m * ROWB + ckh * 16, Ap + (long long)m * lda + ckh * 8);
            cp16(sb + m * ROWB + ckh * 16, Bp + (long long)m * ldb + ckh * 8);
        }
        cp_commit();
    }

    float acc[4][8][4] = {};
    for (int c = 0; c < nch; c++) {
        const int p = c & 1;
        if (c + 1 < nch) {
            const int q = (c + 1) & 1;
            const int k0 = (c + 1) << 6;
            const uint32_t sa = s0 + q * STAGEB, sb = sa + ABUF;
            #pragma unroll
            for (int r = 0; r < 8; r++) {
                int m = cm + r * 16;
                cp16(sa + m * ROWB + ckh * 16, Ap + (long long)m * lda + k0 + ckh * 8);
                cp16(sb + m * ROWB + ckh * 16, Bp + (long long)m * ldb + k0 + ckh * 8);
            }
        }
        cp_commit();
        cp_wait1();
        __syncthreads();

        const uint32_t ab = s0 + p * STAGEB + a_off;
        const uint32_t bb = s0 + p * STAGEB + ABUF + b_off;
        #pragma unroll
        for (int ks = 0; ks < 4; ks++) {
            unsigned af[4][4], bf[8][2];
            #pragma unroll
            for (int i = 0; i < 4; i++)
                ldm4(af[i], ab + i * (16 * ROWB) + ks * 32);
            #pragma unroll
            for (int jp = 0; jp < 4; jp++) {
                unsigned t4[4];
                ldm4(t4, bb + jp * (16 * ROWB) + ks * 32);
                bf[jp * 2][0] = t4[0]; bf[jp * 2][1] = t4[1];
                bf[jp * 2 + 1][0] = t4[2]; bf[jp * 2 + 1][1] = t4[3];
            }
            #pragma unroll
            for (int i = 0; i < 4; i++)
                #pragma unroll
                for (int j = 0; j < 8; j++)
                    mma_f16(acc[i][j], af[i], bf[j]);
        }
        __syncthreads();
    }

    #pragma unroll
    for (int i = 0; i < 4; i++) {
        int r0 = bm + wm + i * 16 + g;
        #pragma unroll
        for (int j = 0; j < 8; j++) {
            int cc = bn + wn + j * 8 + 2 * tg;
            float v0 = acc[i][j][0] * alpha, v1 = acc[i][j][1] * alpha;
            float v2 = acc[i][j][2] * alpha, v3 = acc[i][j][3] * alpha;
            if (biasp) {
                float b0 = biasp[cc], b1 = biasp[cc + 1];
                v0 += b0; v1 += b1; v2 += b0; v3 += b1;
            }
            if (mode == 1) {
                v0 = gelu_tanh(v0); v1 = gelu_tanh(v1);
                v2 = gelu_tanh(v2); v3 = gelu_tanh(v3);
            } else if (mode == 2) {
                const float* q0 = resp + (long long)r0 * ldr + cc;
                const float* q1 = resp + (long long)(r0 + 8) * ldr + cc;
                float g0 = gatep[cc], g1 = gatep[cc + 1];
                v0 = q0[0] + g0 * v0; v1 = q0[1] + g1 * v1;
                v2 = q1[0] + g0 * v2; v3 = q1[1] + g1 * v3;
            }
            if (c_half) {
                __half* C = (__half*)Cp + (long long)blockIdx.z * sC;
                *(__half2*)&C[(long long)r0 * ldc + cc]       = __floats2half2_rn(v0, v1);
                *(__half2*)&C[(long long)(r0 + 8) * ldc + cc] = __floats2half2_rn(v2, v3);
            } else {
                float* C = (float*)Cp + (long long)blockIdx.z * sC;
                float2 o0 = {v0, v1}, o1 = {v2, v3};
                *(float2*)&C[(long long)r0 * ldc + cc]       = o0;
                *(float2*)&C[(long long)(r0 + 8) * ldc + cc] = o1;
            }
        }
    }
}

// ---------------- modulation GEMV: split-K partials ----------------
__global__ void __launch_bounds__(256) mod_split(const float* __restrict__ vec,
                                                 const float* __restrict__ w1,
                                                 const float* __restrict__ w2,
                                                 float* __restrict__ partial) {
    __shared__ float sv[MROWS];
    const float* w = blockIdx.z ? w2 : w1;
    const int i0 = blockIdx.y * MROWS;
    if (threadIdx.x < MROWS) {
        float x = vec[i0 + threadIdx.x];
        sv[threadIdx.x] = x / (1.f + expf(-x));
    }
    __syncthreads();
    const int col = blockIdx.x * 256 + threadIdx.x;
    float acc = 0.f;
    const float* wp = w + (size_t)i0 * MOD6 + col;
    #pragma unroll 8
    for (int i = 0; i < MROWS; i++) acc += sv[i] * wp[(size_t)i * MOD6];
    partial[((size_t)blockIdx.z * MSPLIT + blockIdx.y) * MOD6 + col] = acc;
}

__global__ void __launch_bounds__(256) mod_reduce(const float* __restrict__ partial,
                                                  const float* __restrict__ b1,
                                                  const float* __restrict__ b2,
                                                  float* __restrict__ o1,
                                                  float* __restrict__ o2) {
    const int col = blockIdx.x * 256 + threadIdx.x;
    const int z = blockIdx.y;
    const float* p = partial + (size_t)z * MSPLIT * MOD6 + col;
    float acc = (z ? b2 : b1)[col];
    #pragma unroll
    for (int k = 0; k < MSPLIT; k++) acc += p[(size_t)k * MOD6];
    (z ? o2 : o1)[col] = acc;
}

// ---------------- LayerNorm + modulate (dual-region) -> half ----------------
__global__ void __launch_bounds__(256) ln_mod_kernel(const float* __restrict__ x1,
                                                     const float* __restrict__ x2,
                                                     int split,
                                                     __half* __restrict__ y,
                                                     const float* __restrict__ sh1,
                                                     const float* __restrict__ sc1,
                                                     const float* __restrict__ sh2,
                                                     const float* __restrict__ sc2) {
    __shared__ float s0[32], s1[32];
    int row = blockIdx.x;
    const bool sec = row >= split;
    const float* xr = (sec ? x2 : x1) + (size_t)row * H;
    const float* sh = sec ? sh2 : sh1;
    const float* sc = sec ? sc2 : sc1;
    float s = 0.f, s2 = 0.f;
    for (int j = threadIdx.x; j < H; j += 256) {
        float v = xr[j];
        s += v; s2 += v * v;
    }
    float sum  = block_reduce_sum(s,  s0);
    float sum2 = block_reduce_sum(s2, s1);
    float mean = sum * (1.f / H);
    float var  = sum2 * (1.f / H) - mean * mean;
    float inv  = rsqrtf(var + 1e-6f);
    __half* yr = y + (size_t)row * H;
    for (int j = threadIdx.x * 2; j < H; j += 512) {
        float a = (xr[j]     - mean) * inv * (1.f + sc[j])     + sh[j];
        float b = (xr[j + 1] - mean) * inv * (1.f + sc[j + 1]) + sh[j + 1];
        *(__half2*)&yr[j] = __floats2half2_rn(a, b);
    }
}

// ---------------- QKV postprocess: coalesced; 32 tokens x 1 head per block ----------------
__global__ void __launch_bounds__(256) qkv_post_kernel(const __half* __restrict__ qkv,
                                                       const float* __restrict__ pe,
                                                       const float* __restrict__ nq_i,
                                                       const float* __restrict__ nk_i,
                                                       const float* __restrict__ nq_t,
                                                       const float* __restrict__ nk_t,
                                                       __half* __restrict__ gq,
                                                       __half* __restrict__ gk,
                                                       __half* __restrict__ gv) {
    __shared__ __half vt[128][34];
    const int h = blockIdx.y;
    const int s0 = blockIdx.x * 32;
    const int warp = threadIdx.x >> 5, lane = threadIdx.x & 31;
    const int d0 = lane * 4;

    #pragma unroll
    for (int ti = 0; ti < 4; ti++) {
        const int s = s0 + warp * 4 + ti;
        const __half* base = qkv + (size_t)s * QKV3 + h * HD + d0;
        uint2 qu = *(const uint2*)base;
        uint2 ku = *(const uint2*)(base + H);
        uint2 vu = *(const uint2*)(base + 2 * H);
        __half2 qh0 = *(__half2*)&qu.x, qh1 = *(__half2*)&qu.y;
        __half2 kh0 = *(__half2*)&ku.x, kh1 = *(__half2*)&ku.y;
        float q[4] = {__low2float(qh0), __high2float(qh0), __low2float(qh1), __high2float(qh1)};
        float k[4] = {__low2float(kh0), __high2float(kh0), __low2float(kh1), __high2float(kh1)};
        float sq = q[0]*q[0] + q[1]*q[1] + q[2]*q[2] + q[3]*q[3];
        float sk = k[0]*k[0] + k[1]*k[1] + k[2]*k[2] + k[3]*k[3];
        #pragma unroll
        for (int o = 16; o; o >>= 1) {
            sq += __shfl_xor_sync(0xffffffffu, sq, o);
            sk += __shfl_xor_sync(0xffffffffu, sk, o);
        }
        const float rq = rsqrtf(sq * (1.f / HD) + 1e-6f);
        const float rk = rsqrtf(sk * (1.f / HD) + 1e-6f);
        const bool is_txt = s < LT;
        const float* nq = is_txt ? nq_t : nq_i;
        const float* nk = is_txt ? nk_t : nk_i;
        float qn[4], kn[4];
        #pragma unroll
        for (int e = 0; e < 4; e++) {
            qn[e] = q[e] * rq * nq[d0 + e];
            kn[e] = k[e] * rk * nk[d0 + e];
        }
        const float4 f0 = *(const float4*)(pe + ((size_t)s * 64 + lane * 2) * 4);
        const float4 f1 = *(const float4*)(pe + ((size_t)s * 64 + lane * 2 + 1) * 4);
        float qo[4], ko[4];
        qo[0] = f0.x * qn[0] + f0.y * qn[1]; qo[1] = f0.z * qn[0] + f0.w * qn[1];
        qo[2] = f1.x * qn[2] + f1.y * qn[3]; qo[3] = f1.z * qn[2] + f1.w * qn[3];
        ko[0] = f0.x * kn[0] + f0.y * kn[1]; ko[1] = f0.z * kn[0] + f0.w * kn[1];
        ko[2] = f1.x * kn[2] + f1.y * kn[3]; ko[3] = f1.z * kn[2] + f1.w * kn[3];
        __half2 qw0 = __floats2half2_rn(qo[0], qo[1]), qw1 = __floats2half2_rn(qo[2], qo[3]);
        __half2 kw0 = __floats2half2_rn(ko[0], ko[1]), kw1 = __floats2half2_rn(ko[2], ko[3]);
        const size_t idx = ((size_t)h * L + s) * HD + d0;
        uint2 qst = {*(unsigned*)&qw0, *(unsigned*)&qw1};
        uint2 kst = {*(unsigned*)&kw0, *(unsigned*)&kw1};
        *(uint2*)&gq[idx] = qst;
        *(uint2*)&gk[idx] = kst;
        __half2 vh0 = *(__half2*)&vu.x, vh1 = *(__half2*)&vu.y;
        const int tcol = warp * 4 + ti;
        vt[d0 + 0][tcol] = __low2half(vh0);
        vt[d0 + 1][tcol] = __high2half(vh0);
        vt[d0 + 2][tcol] = __low2half(vh1);
        vt[d0 + 3][tcol] = __high2half(vh1);
    }
    __syncthreads();
    const int d = threadIdx.x >> 1, hf = (threadIdx.x & 1) * 16;
    __half tmp[16];
    #pragma unroll
    for (int i = 0; i < 16; i++) tmp[i] = vt[d][hf + i];
    __half* dst = gv + ((size_t)h * HD + d) * L + s0 + hf;
    *(uint4*)dst       = *(uint4*)tmp;
    *(uint4*)(dst + 8) = *(uint4*)(tmp + 8);
}

// ---------------- softmax ----------------
__global__ void __launch_bounds__(256) softmax_rows(__half* __restrict__ S) {
    __shared__ float s0[32], s1[32];
    __half2* row = (__half2*)(S + (size_t)blockIdx.x * L);
    int t = threadIdx.x;
    float2 v[3];
    #pragma unroll
    for (int i = 0; i < 3; i++) v[i] = __half22float2(row[t + i * 256]);
    float m = fmaxf(fmaxf(fmaxf(v[0].x, v[0].y), fmaxf(v[1].x, v[1].y)), fmaxf(v[2].x, v[2].y));
    m = block_reduce_max(m, s0);
    float sum = 0.f;
    #pragma unroll
    for (int i = 0; i < 3; i++) {
        v[i].x = __expf(v[i].x - m); v[i].y = __expf(v[i].y - m);
        sum += v[i].x + v[i].y;
    }
    sum = block_reduce_sum(sum, s1);
    float inv = 1.f / sum;
    #pragma unroll
    for (int i = 0; i < 3; i++)
        row[t + i * 256] = __floats2half2_rn(v[i].x * inv, v[i].y * inv);
}

// ---------------- launch ----------------
extern "C" void kernel_launch(void* const* d_in, const int* in_sizes, int n_in,
                              void* d_out, int out_size) {
    const float* img      = (const float*)d_in[0];
    const float* txt      = (const float*)d_in[1];
    const float* vec      = (const float*)d_in[2];
    const float* pe       = (const float*)d_in[3];
    const float* mod_w    = (const float*)d_in[4];
    const float* mod_b    = (const float*)d_in[5];
    const float* qkv_w    = (const float*)d_in[6];
    const float* qkv_b    = (const float*)d_in[7];
    const float* norm_q_w = (const float*)d_in[8];
    const float* norm_k_w = (const float*)d_in[9];
    const float* out_w    = (const float*)d_in[10];
    const float* out_b    = (const float*)d_in[11];
    const float* fc1_w    = (const float*)d_in[12];
    const float* fc1_b    = (const float*)d_in[13];
    const float* fc2_w    = (const float*)d_in[14];
    const float* fc2_b    = (const float*)d_in[15];
    const float* mod_c_w  = (const float*)d_in[16];
    const float* mod_c_b  = (const float*)d_in[17];
    const float* qkv_c_w  = (const float*)d_in[18];
    const float* qkv_c_b  = (const float*)d_in[19];
    const float* norm_aq_w= (const float*)d_in[20];
    const float* norm_ak_w= (const float*)d_in[21];
    const float* out_c_w  = (const float*)d_in[22];
    const float* out_c_b  = (const float*)d_in[23];
    const float* fc1_c_w  = (const float*)d_in[24];
    const float* fc1_c_b  = (const float*)d_in[25];
    const float* fc2_c_w  = (const float*)d_in[26];
    const float* fc2_c_b  = (const float*)d_in[27];
    float* out = (float*)d_out;

    float *modi, *modt, *modp, *res2;
    __half *qkvh, *xmod, *qb, *kb, *vb, *Sb, *attnb, *hb, *fc1b;
    __half *qkvw_t, *qkvcw_t, *outw_t, *outcw_t, *fc1w_t, *fc1cw_t, *fc2w_t, *fc2cw_t;
    cudaGetSymbolAddress((void**)&modi,   g_mod_img);
    cudaGetSymbolAddress((void**)&modt,   g_mod_txt);
    cudaGetSymbolAddress((void**)&modp,   g_modp);
    cudaGetSymbolAddress((void**)&res2,   g_res2);
    cudaGetSymbolAddress((void**)&qkvh,   g_qkvh);
    cudaGetSymbolAddress((void**)&xmod,   g_xmod);
    cudaGetSymbolAddress((void**)&qb,     g_q);
    cudaGetSymbolAddress((void**)&kb,     g_k);
    cudaGetSymbolAddress((void**)&vb,     g_v);
    cudaGetSymbolAddress((void**)&Sb,     g_S);
    cudaGetSymbolAddress((void**)&attnb,  g_attn);
    cudaGetSymbolAddress((void**)&hb,     g_hbuf);
    cudaGetSymbolAddress((void**)&fc1b,   g_fc1);
    cudaGetSymbolAddress((void**)&qkvw_t, g_qkvw_t);
    cudaGetSymbolAddress((void**)&qkvcw_t,g_qkvcw_t);
    cudaGetSymbolAddress((void**)&outw_t, g_outw_t);
    cudaGetSymbolAddress((void**)&outcw_t,g_outcw_t);
    cudaGetSymbolAddress((void**)&fc1w_t, g_fc1w_t);
    cudaGetSymbolAddress((void**)&fc1cw_t,g_fc1cw_t);
    cudaGetSymbolAddress((void**)&fc2w_t, g_fc2w_t);
    cudaGetSymbolAddress((void**)&fc2cw_t,g_fc2cw_t);

    cudaFuncSetAttribute(hgemm, cudaFuncAttributeMaxDynamicSharedMemorySize, DSMEM);

    const int BIG = 1 << 30;
    const float* img_off = img - (size_t)LT * H;
    float* out_img_off = out - (size_t)LT * H;
    float* out_txt     = out + (size_t)LI * H;

    // qkv weight pair (one launch), then modulation, ln, qkv GEMM
    wt2_kernel<<<dim3(QKV3/64, H/64, 2), 256>>>(qkv_c_w, qkv_w, qkvcw_t, qkvw_t, H, QKV3);
    mod_split<<<dim3(MOD6/256, MSPLIT, 2), 256>>>(vec, mod_w, mod_c_w, modp);
    mod_reduce<<<dim3(MOD6/256, 2), 256>>>(modp, mod_b, mod_c_b, modi, modt);
    ln_mod_kernel<<<L, 256>>>(txt, img_off, LT, xmod,
                              modt, modt + H, modi, modi + H);

    // qkv GEMM (merged)
    hgemm<<<dim3(L/128, QKV3/128, 1), 128, DSMEM>>>(
        xmod, H, 0, qkvcw_t, qkvw_t, H, 0,
        qkvh, qkvh, QKV3, 0, 1, H, 1.f, LT/128,
        qkv_c_b, qkv_b, nullptr, nullptr, nullptr, nullptr, 0, 0);

    // remaining weight pairs
    wt2_kernel<<<dim3(H/64,    H/64, 2), 256>>>(out_c_w, out_w, outcw_t, outw_t, H, H);
    wt2_kernel<<<dim3(MLPD/64, H/64, 2), 256>>>(fc1_c_w, fc1_w, fc1cw_t, fc1w_t, H, MLPD);
    wt2_kernel<<<dim3(H/64, MLPD/64, 2), 256>>>(fc2_c_w, fc2_w, fc2cw_t, fc2w_t, MLPD, H);

    // rms + rope + head-major split (coalesced)
    {
        dim3 g(L / 32, NH);
        qkv_post_kernel<<<g, 256>>>(qkvh, pe, norm_q_w, norm_k_w, norm_aq_w, norm_ak_w,
                                    qb, kb, vb);
    }

    // S = scale * Q K^T
    hgemm<<<dim3(L/128, L/128, NH), 128, DSMEM>>>(
        qb, HD, (long long)L * HD, kb, kb, HD, (long long)L * HD,
        Sb, Sb, L, (long long)L * L, 1, HD, 0.08838834764831845f, BIG,
        nullptr, nullptr, nullptr, nullptr, nullptr, nullptr, 0, 0);

    // softmax
    softmax_rows<<<NH * L, 256>>>(Sb);

    // O = P @ V
    hgemm<<<dim3(L/128, 1, NH), 128, DSMEM>>>(
        Sb, L, (long long)L * L, vb, vb, L, (long long)HD * L,
        attnb, attnb, H, (long long)HD, 1, L, 1.f, BIG,
        nullptr, nullptr, nullptr, nullptr, nullptr, nullptr, 0, 0);

    // out projection + gated residual (merged)
    hgemm<<<dim3(L/128, H/128, 1), 128, DSMEM>>>(
        attnb, H, 0, outcw_t, outw_t, H, 0,
        res2, res2, H, 0, 0, H, 1.f, LT/128,
        out_c_b, out_b, modt + 2 * H, modi + 2 * H, txt, img_off, H, 2);

    // LN + modulate stage 2 (merged)
    ln_mod_kernel<<<L, 256>>>(res2, res2, LT, hb,
                              modt + 3 * H, modt + 4 * H, modi + 3 * H, modi + 4 * H);

    // fc1 + gelu (merged)
    hgemm<<<dim3(L/128, MLPD/128, 1), 128, DSMEM>>>(
        hb, H, 0, fc1cw_t, fc1w_t, H, 0,
        fc1b, fc1b, MLPD, 0, 1, H, 1.f, LT/128,
        fc1_c_b, fc1_b, nullptr, nullptr, nullptr, nullptr, 0, 1);

    // fc2 + gated residual (merged) -> final output
    hgemm<<<dim3(L/128, H/128, 1), 128, DSMEM>>>(
        fc1b, MLPD, 0, fc2cw_t, fc2w_t, MLPD, 0,
        out_txt, out_img_off, H, 0, 0, MLPD, 1.f, LT/128,
        fc2_c_b, fc2_b, modt + 5 * H, modi + 5 * H, res2, res2, H, 2);

    (void)in_sizes; (void)n_in; (void)out_size;
}

// round 16
// speedup vs baseline: 1.0552x; 1.0552x over previous
#include <cuda_runtime.h>
#include <cuda_fp16.h>
#include <math.h>
#include <stdint.h>

#define H    3072
#define NH   24
#define HD   128
#define MLPD 12288
#define LT   512
#define LI   1024
#define L    1536
#define QKV3 9216
#define MOD6 18432
#define MSPLIT 16
#define MROWS (H / MSPLIT)

#define ROWB   144
#define ABUF   (128 * ROWB)
#define STAGEB (2 * ABUF)
#define DSMEM  (2 * STAGEB)

// flash-attention smem layout
#define QROWB 272                       // 128 halves (256B) + 16 pad
#define FQ_BYTES (128 * QROWB)          // 34816
#define FK_BYTES (64 * QROWB)           // 17408
#define FV_BYTES (128 * ROWB)           // 18432
#define FSTAGE (FK_BYTES + FV_BYTES)    // 35840
#define FSMEM (FQ_BYTES + 2 * FSTAGE)   // 106496

// ---------------- scratch ----------------
__device__ float g_mod_img[MOD6];
__device__ float g_mod_txt[MOD6];
__device__ float g_modp[(size_t)2 * MSPLIT * MOD6];
__device__ float g_res2[(size_t)L * H];
__device__ __align__(16) __half g_qkvh[(size_t)L * QKV3];
__device__ __align__(16) __half g_xmod[(size_t)L * H];
__device__ __align__(16) __half g_q   [(size_t)NH * L * HD];
__device__ __align__(16) __half g_k   [(size_t)NH * L * HD];
__device__ __align__(16) __half g_v   [(size_t)NH * HD * L];
__device__ __align__(16) __half g_attn[(size_t)L * H];
__device__ __align__(16) __half g_hbuf[(size_t)L * H];
__device__ __align__(16) __half g_fc1 [(size_t)L * MLPD];
__device__ __align__(16) __half g_qkvw_t [(size_t)QKV3 * H];
__device__ __align__(16) __half g_qkvcw_t[(size_t)QKV3 * H];
__device__ __align__(16) __half g_outw_t [(size_t)H * H];
__device__ __align__(16) __half g_outcw_t[(size_t)H * H];
__device__ __align__(16) __half g_fc1w_t [(size_t)MLPD * H];
__device__ __align__(16) __half g_fc1cw_t[(size_t)MLPD * H];
__device__ __align__(16) __half g_fc2w_t [(size_t)H * MLPD];
__device__ __align__(16) __half g_fc2cw_t[(size_t)H * MLPD];

// ---------------- ptx helpers ----------------
__device__ __forceinline__ uint32_t smem_u32(const void* p) {
    uint32_t a;
    asm("{ .reg .u64 t; cvta.to.shared.u64 t, %1; cvt.u32.u64 %0, t; }" : "=r"(a) : "l"(p));
    return a;
}
__device__ __forceinline__ void cp16(uint32_t dst, const void* src) {
    asm volatile("cp.async.cg.shared.global [%0], [%1], 16;" :: "r"(dst), "l"(src));
}
__device__ __forceinline__ void cp_commit() { asm volatile("cp.async.commit_group;"); }
__device__ __forceinline__ void cp_wait1()  { asm volatile("cp.async.wait_group 1;"); }
__device__ __forceinline__ void ldm4(unsigned* r, uint32_t a) {
    asm volatile("ldmatrix.sync.aligned.m8n8.x4.shared.b16 {%0,%1,%2,%3}, [%4];"
                 : "=r"(r[0]), "=r"(r[1]), "=r"(r[2]), "=r"(r[3]) : "r"(a));
}
__device__ __forceinline__ void mma_f16(float* c, const unsigned* a, const unsigned* b) {
    asm volatile(
        "mma.sync.aligned.m16n8k16.row.col.f32.f16.f16.f32 "
        "{%0,%1,%2,%3}, {%4,%5,%6,%7}, {%8,%9}, {%0,%1,%2,%3};\n"
        : "+f"(c[0]), "+f"(c[1]), "+f"(c[2]), "+f"(c[3])
        : "r"(a[0]), "r"(a[1]), "r"(a[2]), "r"(a[3]), "r"(b[0]), "r"(b[1]));
}
__device__ __forceinline__ float gelu_tanh(float x) {
    return 0.5f * x * (1.f + tanhf(0.7978845608028654f * (x + 0.044715f * x * x * x)));
}
__device__ __forceinline__ unsigned packh2(float lo, float hi) {
    __half2 h = __floats2half2_rn(lo, hi);
    return *reinterpret_cast<unsigned*>(&h);
}

// ---------------- reduce helpers ----------------
__device__ __forceinline__ float block_reduce_sum(float v, float* sh) {
    #pragma unroll
    for (int o = 16; o; o >>= 1) v += __shfl_xor_sync(0xffffffffu, v, o);
    int w = threadIdx.x >> 5;
    if ((threadIdx.x & 31) == 0) sh[w] = v;
    __syncthreads();
    if (threadIdx.x < 32) {
        float x = (threadIdx.x < (blockDim.x >> 5)) ? sh[threadIdx.x] : 0.f;
        #pragma unroll
        for (int o = 16; o; o >>= 1) x += __shfl_xor_sync(0xffffffffu, x, o);
        if (threadIdx.x == 0) sh[0] = x;
    }
    __syncthreads();
    return sh[0];
}

// ---------------- weight convert+transpose (round-10 proven) ----------------
__global__ void __launch_bounds__(256) wt_kernel(const float* __restrict__ W,
                                                 __half* __restrict__ Wt,
                                                 int K, int N) {
    __shared__ float t[64][33];
    const int n0 = blockIdx.x * 32;
    const int k0 = blockIdx.y * 64;
    const int tid = threadIdx.x;
    #pragma unroll
    for (int r = 0; r < 2; r++) {
        int idx = tid + r * 256;
        int k = idx >> 3, n4 = (idx & 7) * 4;
        float4 v = *(const float4*)&W[(size_t)(k0 + k) * N + n0 + n4];
        t[k][n4] = v.x; t[k][n4 + 1] = v.y; t[k][n4 + 2] = v.z; t[k][n4 + 3] = v.w;
    }
    __syncthreads();
    int n = tid >> 3, kq = (tid & 7) * 8;
    __half hv[8];
    #pragma unroll
    for (int i = 0; i < 8; i++) hv[i] = __float2half(t[kq + i][n]);
    *(uint4*)&Wt[(size_t)(n0 + n) * K + k0 + kq] = *(uint4*)hv;
}

// ================= fp16 NT GEMM: 128x128 block, 4 warps, 64x64 warp tile =================
__global__ void __launch_bounds__(128, 2) hgemm(const __half* __restrict__ A, int lda, long long sA,
                                                const __half* __restrict__ B, const __half* __restrict__ B2,
                                                int ldb, long long sB,
                                                void* __restrict__ Cv, void* __restrict__ Cv2,
                                                int ldc, long long sC, int c_half,
                                                int K, float alpha, int mSplit,
                                                const float* __restrict__ bias, const float* __restrict__ bias2,
                                                const float* __restrict__ gate, const float* __restrict__ gate2,
                                                const float* __restrict__ residual, const float* __restrict__ residual2,
                                                int ldr, int mode) {
    extern __shared__ char smem[];
    const int tid  = threadIdx.x;
    const int warp = tid >> 5, lane = tid & 31;
    const int g = lane >> 2, tg = lane & 3;
    const int bm = blockIdx.x * 128, bn = blockIdx.y * 128;
    const int wm = (warp >> 1) * 64, wn = (warp & 1) * 64;

    const bool second = (int)blockIdx.x >= mSplit;
    const __half* Bp = second ? B2 : B;
    const float* biasp = second ? bias2 : bias;
    const float* gatep = second ? gate2 : gate;
    const float* resp  = second ? residual2 : residual;
    void* Cp = second ? Cv2 : Cv;

    const __half* Ap = A + (long long)blockIdx.z * sA + (long long)bm * lda;
    Bp += (long long)blockIdx.z * sB + (long long)bn * ldb;

    const uint32_t s0 = smem_u32(smem);
    const int cm = tid >> 3, ckh = tid & 7;

    const uint32_t a_off = (uint32_t)((wm + (lane & 7) + ((lane >> 3) & 1) * 8) * ROWB + (lane >> 4) * 16);
    const uint32_t b_off = (uint32_t)((wn + (lane & 7) + ((lane >> 4) & 1) * 8) * ROWB + ((lane >> 3) & 1) * 16);

    const int nch = K >> 6;

    {
        const uint32_t sa = s0, sb = s0 + ABUF;
        #pragma unroll
        for (int r = 0; r < 8; r++) {
            int m = cm + r * 16;
            cp16(sa + m * ROWB + ckh * 16, Ap + (long long)m * lda + ckh * 8);
            cp16(sb + m * ROWB + ckh * 16, Bp + (long long)m * ldb + ckh * 8);
        }
        cp_commit();
    }

    float acc[4][8][4] = {};
    for (int c = 0; c < nch; c++) {
        const int p = c & 1;
        if (c + 1 < nch) {
            const int q = (c + 1) & 1;
            const int k0 = (c + 1) << 6;
            const uint32_t sa = s0 + q * STAGEB, sb = sa + ABUF;
            #pragma unroll
            for (int r = 0; r < 8; r++) {
                int m = cm + r * 16;
                cp16(sa + m * ROWB + ckh * 16, Ap + (long long)m * lda + k0 + ckh * 8);
                cp16(sb + m * ROWB + ckh * 16, Bp + (long long)m * ldb + k0 + ckh * 8);
            }
        }
        cp_commit();
        cp_wait1();
        __syncthreads();

        const uint32_t ab = s0 + p * STAGEB + a_off;
        const uint32_t bb = s0 + p * STAGEB + ABUF + b_off;
        #pragma unroll
        for (int ks = 0; ks < 4; ks++) {
            unsigned af[4][4], bf[8][2];
            #pragma unroll
            for (int i = 0; i < 4; i++)
                ldm4(af[i], ab + i * (16 * ROWB) + ks * 32);
            #pragma unroll
            for (int jp = 0; jp < 4; jp++) {
                unsigned t4[4];
                ldm4(t4, bb + jp * (16 * ROWB) + ks * 32);
                bf[jp * 2][0] = t4[0]; bf[jp * 2][1] = t4[1];
                bf[jp * 2 + 1][0] = t4[2]; bf[jp * 2 + 1][1] = t4[3];
            }
            #pragma unroll
            for (int i = 0; i < 4; i++)
                #pragma unroll
                for (int j = 0; j < 8; j++)
                    mma_f16(acc[i][j], af[i], bf[j]);
        }
        __syncthreads();
    }

    #pragma unroll
    for (int i = 0; i < 4; i++) {
        int r0 = bm + wm + i * 16 + g;
        #pragma unroll
        for (int j = 0; j < 8; j++) {
            int cc = bn + wn + j * 8 + 2 * tg;
            float v0 = acc[i][j][0] * alpha, v1 = acc[i][j][1] * alpha;
            float v2 = acc[i][j][2] * alpha, v3 = acc[i][j][3] * alpha;
            if (biasp) {
                float b0 = biasp[cc], b1 = biasp[cc + 1];
                v0 += b0; v1 += b1; v2 += b0; v3 += b1;
            }
            if (mode == 1) {
                v0 = gelu_tanh(v0); v1 = gelu_tanh(v1);
                v2 = gelu_tanh(v2); v3 = gelu_tanh(v3);
            } else if (mode == 2) {
                const float* q0 = resp + (long long)r0 * ldr + cc;
                const float* q1 = resp + (long long)(r0 + 8) * ldr + cc;
                float g0 = gatep[cc], g1 = gatep[cc + 1];
                v0 = q0[0] + g0 * v0; v1 = q0[1] + g1 * v1;
                v2 = q1[0] + g0 * v2; v3 = q1[1] + g1 * v3;
            }
            if (c_half) {
                __half* C = (__half*)Cp + (long long)blockIdx.z * sC;
                *(__half2*)&C[(long long)r0 * ldc + cc]       = __floats2half2_rn(v0, v1);
                *(__half2*)&C[(long long)(r0 + 8) * ldc + cc] = __floats2half2_rn(v2, v3);
            } else {
                float* C = (float*)Cp + (long long)blockIdx.z * sC;
                float2 o0 = {v0, v1}, o1 = {v2, v3};
                *(float2*)&C[(long long)r0 * ldc + cc]       = o0;
                *(float2*)&C[(long long)(r0 + 8) * ldc + cc] = o1;
            }
        }
    }
}

// ================= fused flash attention =================
// grid (L/128, NH), 256 threads. Q tile 128xHD in smem; KV in 64-token chunks.
// Per warp: 16 Q rows x full KV width. Output: attnb[token][h*HD + d] (half).
__global__ void __launch_bounds__(256, 1) fattn(const __half* __restrict__ gq,
                                                const __half* __restrict__ gk,
                                                const __half* __restrict__ gv,
                                                __half* __restrict__ attnb) {
    extern __shared__ char smem[];
    const int tid  = threadIdx.x;
    const int warp = tid >> 5, lane = tid & 31;
    const int g = lane >> 2, tg = lane & 3;
    const int bm = blockIdx.x * 128;
    const int h  = blockIdx.y;
    const float alpha = 0.08838834764831845f;

    const __half* Qg = gq + ((size_t)h * L + bm) * HD;
    const __half* Kg = gk + (size_t)h * L * HD;
    const __half* Vg = gv + (size_t)h * HD * L;

    const uint32_t s0 = smem_u32(smem);
    const uint32_t sq = s0;

    // ---- stage Q (128 rows x 128 halves) ----
    #pragma unroll
    for (int r = 0; r < 8; r++) {
        int id = tid + r * 256;
        int row = id >> 4, ch = id & 15;
        cp16(sq + row * QROWB + ch * 16, Qg + (size_t)row * HD + ch * 8);
    }
    // ---- stage KV chunk 0 ----
    {
        const uint32_t sk = s0 + FQ_BYTES, sv = sk + FK_BYTES;
        #pragma unroll
        for (int r = 0; r < 4; r++) {
            int id = tid + r * 256;
            int row = id >> 4, ch = id & 15;
            cp16(sk + row * QROWB + ch * 16, Kg + (size_t)row * HD + ch * 8);
        }
        #pragma unroll
        for (int r = 0; r < 4; r++) {
            int id = tid + r * 256;
            int row = id >> 3, ch = id & 7;
            cp16(sv + row * ROWB + ch * 16, Vg + (size_t)row * L + ch * 8);
        }
        cp_commit();
    }

    const uint32_t a_off  = (uint32_t)((warp * 16 + (lane & 7) + ((lane >> 3) & 1) * 8) * QROWB + (lane >> 4) * 16);
    const uint32_t bk_off = (uint32_t)(((lane & 7) + ((lane >> 4) & 1) * 8) * QROWB + ((lane >> 3) & 1) * 16);
    const uint32_t bv_off = (uint32_t)(((lane & 7) + ((lane >> 4) & 1) * 8) * ROWB  + ((lane >> 3) & 1) * 16);

    float o_acc[16][4] = {};
    float m0 = -3.0e38f, m1 = -3.0e38f;
    float l0 = 0.f, l1 = 0.f;

    const int NCH = L / 64;   // 24
    for (int c = 0; c < NCH; c++) {
        const int p = c & 1;
        // issue chunk c+1
        if (c + 1 < NCH) {
            const int q = (c + 1) & 1;
            const int n0 = (c + 1) * 64;
            const uint32_t sk = s0 + FQ_BYTES + q * FSTAGE, sv = sk + FK_BYTES;
            #pragma unroll
            for (int r = 0; r < 4; r++) {
                int id = tid + r * 256;
                int row = id >> 4, ch = id & 15;
                cp16(sk + row * QROWB + ch * 16, Kg + (size_t)(n0 + row) * HD + ch * 8);
            }
            #pragma unroll
            for (int r = 0; r < 4; r++) {
                int id = tid + r * 256;
                int row = id >> 3, ch = id & 7;
                cp16(sv + row * ROWB + ch * 16, Vg + (size_t)row * L + n0 + ch * 8);
            }
        }
        cp_commit();
        cp_wait1();
        __syncthreads();

        const uint32_t skb = s0 + FQ_BYTES + p * FSTAGE;
        const uint32_t svb = skb + FK_BYTES;

        // ---- S = alpha * Q K^T  (16 rows x 64 cols per warp) ----
        float sacc[8][4] = {};
        #pragma unroll
        for (int ks = 0; ks < 8; ks++) {
            unsigned af[4], bf[8][2];
            ldm4(af, sq + a_off + ks * 32);
            #pragma unroll
            for (int jp = 0; jp < 4; jp++) {
                unsigned t4[4];
                ldm4(t4, skb + bk_off + jp * (16 * QROWB) + ks * 32);
                bf[jp * 2][0] = t4[0]; bf[jp * 2][1] = t4[1];
                bf[jp * 2 + 1][0] = t4[2]; bf[jp * 2 + 1][1] = t4[3];
            }
            #pragma unroll
            for (int j = 0; j < 8; j++)
                mma_f16(sacc[j], af, bf[j]);
        }

        // ---- online softmax ----
        float cm0 = -3.0e38f, cm1 = -3.0e38f;
        #pragma unroll
        for (int j = 0; j < 8; j++) {
            sacc[j][0] *= alpha; sacc[j][1] *= alpha;
            sacc[j][2] *= alpha; sacc[j][3] *= alpha;
            cm0 = fmaxf(cm0, fmaxf(sacc[j][0], sacc[j][1]));
            cm1 = fmaxf(cm1, fmaxf(sacc[j][2], sacc[j][3]));
        }
        cm0 = fmaxf(cm0, __shfl_xor_sync(0xffffffffu, cm0, 1));
        cm0 = fmaxf(cm0, __shfl_xor_sync(0xffffffffu, cm0, 2));
        cm1 = fmaxf(cm1, __shfl_xor_sync(0xffffffffu, cm1, 1));
        cm1 = fmaxf(cm1, __shfl_xor_sync(0xffffffffu, cm1, 2));
        const float mn0 = fmaxf(m0, cm0), mn1 = fmaxf(m1, cm1);
        const float sc0 = __expf(m0 - mn0), sc1 = __expf(m1 - mn1);
        m0 = mn0; m1 = mn1;

        float rs0 = 0.f, rs1 = 0.f;
        unsigned pf[4][4];
        #pragma unroll
        for (int jj = 0; jj < 4; jj++) {
            float p00 = __expf(sacc[2*jj][0]   - mn0), p01 = __expf(sacc[2*jj][1]   - mn0);
            float p02 = __expf(sacc[2*jj][2]   - mn1), p03 = __expf(sacc[2*jj][3]   - mn1);
            float p10 = __expf(sacc[2*jj+1][0] - mn0), p11 = __expf(sacc[2*jj+1][1] - mn0);
            float p12 = __expf(sacc[2*jj+1][2] - mn1), p13 = __expf(sacc[2*jj+1][3] - mn1);
            rs0 += p00 + p01 + p10 + p11;
            rs1 += p02 + p03 + p12 + p13;
            pf[jj][0] = packh2(p00, p01);
            pf[jj][1] = packh2(p02, p03);
            pf[jj][2] = packh2(p10, p11);
            pf[jj][3] = packh2(p12, p13);
        }
        rs0 += __shfl_xor_sync(0xffffffffu, rs0, 1);
        rs0 += __shfl_xor_sync(0xffffffffu, rs0, 2);
        rs1 += __shfl_xor_sync(0xffffffffu, rs1, 1);
        rs1 += __shfl_xor_sync(0xffffffffu, rs1, 2);
        l0 = l0 * sc0 + rs0;
        l1 = l1 * sc1 + rs1;
        #pragma unroll
        for (int j = 0; j < 16; j++) {
            o_acc[j][0] *= sc0; o_acc[j][1] *= sc0;
            o_acc[j][2] *= sc1; o_acc[j][3] *= sc1;
        }

        // ---- O += P V  (k = 64 chunk tokens, n = 128 dims) ----
        #pragma unroll
        for (int kk = 0; kk < 4; kk++) {
            unsigned bf[16][2];
            #pragma unroll
            for (int jp = 0; jp < 8; jp++) {
                unsigned t4[4];
                ldm4(t4, svb + bv_off + jp * (16 * ROWB) + kk * 32);
                bf[jp * 2][0] = t4[0]; bf[jp * 2][1] = t4[1];
                bf[jp * 2 + 1][0] = t4[2]; bf[jp * 2 + 1][1] = t4[3];
            }
            #pragma unroll
            for (int j = 0; j < 16; j++)
                mma_f16(o_acc[j], pf[kk], bf[j]);
        }
        __syncthreads();
    }

    // ---- epilogue ----
    const float inv0 = 1.f / l0, inv1 = 1.f / l1;
    const int row0 = bm + warp * 16 + g;
    __half* d0 = attnb + (size_t)row0 * H + h * HD;
    __half* d1 = attnb + (size_t)(row0 + 8) * H + h * HD;
    #pragma unroll
    for (int j = 0; j < 16; j++) {
        int cc = j * 8 + 2 * tg;
        *(__half2*)&d0[cc] = __floats2half2_rn(o_acc[j][0] * inv0, o_acc[j][1] * inv0);
        *(__half2*)&d1[cc] = __floats2half2_rn(o_acc[j][2] * inv1, o_acc[j][3] * inv1);
    }
}

// ---------------- modulation GEMV: split-K partials ----------------
__global__ void __launch_bounds__(256) mod_split(const float* __restrict__ vec,
                                                 const float* __restrict__ w1,
                                                 const float* __restrict__ w2,
                                                 float* __restrict__ partial) {
    __shared__ float sv[MROWS];
    const float* w = blockIdx.z ? w2 : w1;
    const int i0 = blockIdx.y * MROWS;
    if (threadIdx.x < MROWS) {
        float x = vec[i0 + threadIdx.x];
        sv[threadIdx.x] = x / (1.f + expf(-x));
    }
    __syncthreads();
    const int col = blockIdx.x * 256 + threadIdx.x;
    float acc = 0.f;
    const float* wp = w + (size_t)i0 * MOD6 + col;
    #pragma unroll 8
    for (int i = 0; i < MROWS; i++) acc += sv[i] * wp[(size_t)i * MOD6];
    partial[((size_t)blockIdx.z * MSPLIT + blockIdx.y) * MOD6 + col] = acc;
}

__global__ void __launch_bounds__(256) mod_reduce(const float* __restrict__ partial,
                                                  const float* __restrict__ b1,
                                                  const float* __restrict__ b2,
                                                  float* __restrict__ o1,
                                                  float* __restrict__ o2) {
    const int col = blockIdx.x * 256 + threadIdx.x;
    const int z = blockIdx.y;
    const float* p = partial + (size_t)z * MSPLIT * MOD6 + col;
    float acc = (z ? b2 : b1)[col];
    #pragma unroll
    for (int k = 0; k < MSPLIT; k++) acc += p[(size_t)k * MOD6];
    (z ? o2 : o1)[col] = acc;
}

// ---------------- LayerNorm + modulate (dual-region) -> half ----------------
__global__ void __launch_bounds__(256) ln_mod_kernel(const float* __restrict__ x1,
                                                     const float* __restrict__ x2,
                                                     int split,
                                                     __half* __restrict__ y,
                                                     const float* __restrict__ sh1,
                                                     const float* __restrict__ sc1,
                                                     const float* __restrict__ sh2,
                                                     const float* __restrict__ sc2) {
    __shared__ float s0[32], s1[32];
    int row = blockIdx.x;
    const bool sec = row >= split;
    const float* xr = (sec ? x2 : x1) + (size_t)row * H;
    const float* sh = sec ? sh2 : sh1;
    const float* sc = sec ? sc2 : sc1;
    float s = 0.f, s2 = 0.f;
    for (int j = threadIdx.x; j < H; j += 256) {
        float v = xr[j];
        s += v; s2 += v * v;
    }
    float sum  = block_reduce_sum(s,  s0);
    float sum2 = block_reduce_sum(s2, s1);
    float mean = sum * (1.f / H);
    float var  = sum2 * (1.f / H) - mean * mean;
    float inv  = rsqrtf(var + 1e-6f);
    __half* yr = y + (size_t)row * H;
    for (int j = threadIdx.x * 2; j < H; j += 512) {
        float a = (xr[j]     - mean) * inv * (1.f + sc[j])     + sh[j];
        float b = (xr[j + 1] - mean) * inv * (1.f + sc[j + 1]) + sh[j + 1];
        *(__half2*)&yr[j] = __floats2half2_rn(a, b);
    }
}

// ---------------- QKV postprocess: coalesced; 32 tokens x 1 head per block ----------------
__global__ void __launch_bounds__(256) qkv_post_kernel(const __half* __restrict__ qkv,
                                                       const float* __restrict__ pe,
                                                       const float* __restrict__ nq_i,
                                                       const float* __restrict__ nk_i,
                                                       const float* __restrict__ nq_t,
                                                       const float* __restrict__ nk_t,
                                                       __half* __restrict__ gq,
                                                       __half* __restrict__ gk,
                                                       __half* __restrict__ gv) {
    __shared__ __half vt[128][34];
    const int h = blockIdx.y;
    const int s0 = blockIdx.x * 32;
    const int warp = threadIdx.x >> 5, lane = threadIdx.x & 31;
    const int d0 = lane * 4;

    #pragma unroll
    for (int ti = 0; ti < 4; ti++) {
        const int s = s0 + warp * 4 + ti;
        const __half* base = qkv + (size_t)s * QKV3 + h * HD + d0;
        uint2 qu = *(const uint2*)base;
        uint2 ku = *(const uint2*)(base + H);
        uint2 vu = *(const uint2*)(base + 2 * H);
        __half2 qh0 = *(__half2*)&qu.x, qh1 = *(__half2*)&qu.y;
        __half2 kh0 = *(__half2*)&ku.x, kh1 = *(__half2*)&ku.y;
        float q[4] = {__low2float(qh0), __high2float(qh0), __low2float(qh1), __high2float(qh1)};
        float k[4] = {__low2float(kh0), __high2float(kh0), __low2float(kh1), __high2float(kh1)};
        float sq = q[0]*q[0] + q[1]*q[1] + q[2]*q[2] + q[3]*q[3];
        float sk = k[0]*k[0] + k[1]*k[1] + k[2]*k[2] + k[3]*k[3];
        #pragma unroll
        for (int o = 16; o; o >>= 1) {
            sq += __shfl_xor_sync(0xffffffffu, sq, o);
            sk += __shfl_xor_sync(0xffffffffu, sk, o);
        }
        const float rq = rsqrtf(sq * (1.f / HD) + 1e-6f);
        const float rk = rsqrtf(sk * (1.f / HD) + 1e-6f);
        const bool is_txt = s < LT;
        const float* nq = is_txt ? nq_t : nq_i;
        const float* nk = is_txt ? nk_t : nk_i;
        float qn[4], kn[4];
        #pragma unroll
        for (int e = 0; e < 4; e++) {
            qn[e] = q[e] * rq * nq[d0 + e];
            kn[e] = k[e] * rk * nk[d0 + e];
        }
        const float4 f0 = *(const float4*)(pe + ((size_t)s * 64 + lane * 2) * 4);
        const float4 f1 = *(const float4*)(pe + ((size_t)s * 64 + lane * 2 + 1) * 4);
        float qo[4], ko[4];
        qo[0] = f0.x * qn[0] + f0.y * qn[1]; qo[1] = f0.z * qn[0] + f0.w * qn[1];
        qo[2] = f1.x * qn[2] + f1.y * qn[3]; qo[3] = f1.z * qn[2] + f1.w * qn[3];
        ko[0] = f0.x * kn[0] + f0.y * kn[1]; ko[1] = f0.z * kn[0] + f0.w * kn[1];
        ko[2] = f1.x * kn[2] + f1.y * kn[3]; ko[3] = f1.z * kn[2] + f1.w * kn[3];
        __half2 qw0 = __floats2half2_rn(qo[0], qo[1]), qw1 = __floats2half2_rn(qo[2], qo[3]);
        __half2 kw0 = __floats2half2_rn(ko[0], ko[1]), kw1 = __floats2half2_rn(ko[2], ko[3]);
        const size_t idx = ((size_t)h * L + s) * HD + d0;
        uint2 qst = {*(unsigned*)&qw0, *(unsigned*)&qw1};
        uint2 kst = {*(unsigned*)&kw0, *(unsigned*)&kw1};
        *(uint2*)&gq[idx] = qst;
        *(uint2*)&gk[idx] = kst;
        __half2 vh0 = *(__half2*)&vu.x, vh1 = *(__half2*)&vu.y;
        const int tcol = warp * 4 + ti;
        vt[d0 + 0][tcol] = __low2half(vh0);
        vt[d0 + 1][tcol] = __high2half(vh0);
        vt[d0 + 2][tcol] = __low2half(vh1);
        vt[d0 + 3][tcol] = __high2half(vh1);
    }
    __syncthreads();
    const int d = threadIdx.x >> 1, hf = (threadIdx.x & 1) * 16;
    __half tmp[16];
    #pragma unroll
    for (int i = 0; i < 16; i++) tmp[i] = vt[d][hf + i];
    __half* dst = gv + ((size_t)h * HD + d) * L + s0 + hf;
    *(uint4*)dst       = *(uint4*)tmp;
    *(uint4*)(dst + 8) = *(uint4*)(tmp + 8);
}

// ---------------- launch ----------------
extern "C" void kernel_launch(void* const* d_in, const int* in_sizes, int n_in,
                              void* d_out, int out_size) {
    const float* img      = (const float*)d_in[0];
    const float* txt      = (const float*)d_in[1];
    const float* vec      = (const float*)d_in[2];
    const float* pe       = (const float*)d_in[3];
    const float* mod_w    = (const float*)d_in[4];
    const float* mod_b    = (const float*)d_in[5];
    const float* qkv_w    = (const float*)d_in[6];
    const float* qkv_b    = (const float*)d_in[7];
    const float* norm_q_w = (const float*)d_in[8];
    const float* norm_k_w = (const float*)d_in[9];
    const float* out_w    = (const float*)d_in[10];
    const float* out_b    = (const float*)d_in[11];
    const float* fc1_w    = (const float*)d_in[12];
    const float* fc1_b    = (const float*)d_in[13];
    const float* fc2_w    = (const float*)d_in[14];
    const float* fc2_b    = (const float*)d_in[15];
    const float* mod_c_w  = (const float*)d_in[16];
    const float* mod_c_b  = (const float*)d_in[17];
    const float* qkv_c_w  = (const float*)d_in[18];
    const float* qkv_c_b  = (const float*)d_in[19];
    const float* norm_aq_w= (const float*)d_in[20];
    const float* norm_ak_w= (const float*)d_in[21];
    const float* out_c_w  = (const float*)d_in[22];
    const float* out_c_b  = (const float*)d_in[23];
    const float* fc1_c_w  = (const float*)d_in[24];
    const float* fc1_c_b  = (const float*)d_in[25];
    const float* fc2_c_w  = (const float*)d_in[26];
    const float* fc2_c_b  = (const float*)d_in[27];
    float* out = (float*)d_out;

    float *modi, *modt, *modp, *res2;
    __half *qkvh, *xmod, *qb, *kb, *vb, *attnb, *hb, *fc1b;
    __half *qkvw_t, *qkvcw_t, *outw_t, *outcw_t, *fc1w_t, *fc1cw_t, *fc2w_t, *fc2cw_t;
    cudaGetSymbolAddress((void**)&modi,   g_mod_img);
    cudaGetSymbolAddress((void**)&modt,   g_mod_txt);
    cudaGetSymbolAddress((void**)&modp,   g_modp);
    cudaGetSymbolAddress((void**)&res2,   g_res2);
    cudaGetSymbolAddress((void**)&qkvh,   g_qkvh);
    cudaGetSymbolAddress((void**)&xmod,   g_xmod);
    cudaGetSymbolAddress((void**)&qb,     g_q);
    cudaGetSymbolAddress((void**)&kb,     g_k);
    cudaGetSymbolAddress((void**)&vb,     g_v);
    cudaGetSymbolAddress((void**)&attnb,  g_attn);
    cudaGetSymbolAddress((void**)&hb,     g_hbuf);
    cudaGetSymbolAddress((void**)&fc1b,   g_fc1);
    cudaGetSymbolAddress((void**)&qkvw_t, g_qkvw_t);
    cudaGetSymbolAddress((void**)&qkvcw_t,g_qkvcw_t);
    cudaGetSymbolAddress((void**)&outw_t, g_outw_t);
    cudaGetSymbolAddress((void**)&outcw_t,g_outcw_t);
    cudaGetSymbolAddress((void**)&fc1w_t, g_fc1w_t);
    cudaGetSymbolAddress((void**)&fc1cw_t,g_fc1cw_t);
    cudaGetSymbolAddress((void**)&fc2w_t, g_fc2w_t);
    cudaGetSymbolAddress((void**)&fc2cw_t,g_fc2cw_t);

    cudaFuncSetAttribute(hgemm, cudaFuncAttributeMaxDynamicSharedMemorySize, DSMEM);
    cudaFuncSetAttribute(fattn, cudaFuncAttributeMaxDynamicSharedMemorySize, FSMEM);

    const float* img_off = img - (size_t)LT * H;
    float* out_img_off = out - (size_t)LT * H;
    float* out_txt     = out + (size_t)LI * H;

    // qkv weight transposes, modulation, ln, qkv GEMM
    wt_kernel<<<dim3(QKV3/32, H/64), 256>>>(qkv_c_w, qkvcw_t, H, QKV3);
    wt_kernel<<<dim3(QKV3/32, H/64), 256>>>(qkv_w,   qkvw_t,  H, QKV3);
    mod_split<<<dim3(MOD6/256, MSPLIT, 2), 256>>>(vec, mod_w, mod_c_w, modp);
    mod_reduce<<<dim3(MOD6/256, 2), 256>>>(modp, mod_b, mod_c_b, modi, modt);
    ln_mod_kernel<<<L, 256>>>(txt, img_off, LT, xmod,
                              modt, modt + H, modi, modi + H);

    hgemm<<<dim3(L/128, QKV3/128, 1), 128, DSMEM>>>(
        xmod, H, 0, qkvcw_t, qkvw_t, H, 0,
        qkvh, qkvh, QKV3, 0, 1, H, 1.f, LT/128,
        qkv_c_b, qkv_b, nullptr, nullptr, nullptr, nullptr, 0, 0);

    wt_kernel<<<dim3(H/32,    H/64), 256>>>(out_c_w, outcw_t, H, H);
    wt_kernel<<<dim3(H/32,    H/64), 256>>>(out_w,   outw_t,  H, H);
    wt_kernel<<<dim3(MLPD/32, H/64), 256>>>(fc1_c_w, fc1cw_t, H, MLPD);
    wt_kernel<<<dim3(MLPD/32, H/64), 256>>>(fc1_w,   fc1w_t,  H, MLPD);
    wt_kernel<<<dim3(H/32, MLPD/64), 256>>>(fc2_c_w, fc2cw_t, MLPD, H);
    wt_kernel<<<dim3(H/32, MLPD/64), 256>>>(fc2_w,   fc2w_t,  MLPD, H);

    {
        dim3 g(L / 32, NH);
        qkv_post_kernel<<<g, 256>>>(qkvh, pe, norm_q_w, norm_k_w, norm_aq_w, norm_ak_w,
                                    qb, kb, vb);
    }

    // fused flash attention (replaces QK gemm + softmax + PV gemm)
    fattn<<<dim3(L/128, NH), 256, FSMEM>>>(qb, kb, vb, attnb);

    // out projection + gated residual (merged)
    hgemm<<<dim3(L/128, H/128, 1), 128, DSMEM>>>(
        attnb, H, 0, outcw_t, outw_t, H, 0,
        res2, res2, H, 0, 0, H, 1.f, LT/128,
        out_c_b, out_b, modt + 2 * H, modi + 2 * H, txt, img_off, H, 2);

    // LN + modulate stage 2 (merged)
    ln_mod_kernel<<<L, 256>>>(res2, res2, LT, hb,
                              modt + 3 * H, modt + 4 * H, modi + 3 * H, modi + 4 * H);

    // fc1 + gelu (merged)
    hgemm<<<dim3(L/128, MLPD/128, 1), 128, DSMEM>>>(
        hb, H, 0, fc1cw_t, fc1w_t, H, 0,
        fc1b, fc1b, MLPD, 0, 1, H, 1.f, LT/128,
        fc1_c_b, fc1_b, nullptr, nullptr, nullptr, nullptr, 0, 1);

    // fc2 + gated residual (merged) -> final output
    hgemm<<<dim3(L/128, H/128, 1), 128, DSMEM>>>(
        fc1b, MLPD, 0, fc2cw_t, fc2w_t, MLPD, 0,
        out_txt, out_img_off, H, 0, 0, MLPD, 1.f, LT/128,
        fc2_c_b, fc2_b, modt + 5 * H, modi + 5 * H, res2, res2, H, 2);

    (void)in_sizes; (void)n_in; (void)out_size;
}

// round 17
// speedup vs baseline: 1.0717x; 1.0156x over previous
#include <cuda_runtime.h>
#include <cuda_fp16.h>
#include <math.h>
#include <stdint.h>

#define H    3072
#define NH   24
#define HD   128
#define MLPD 12288
#define LT   512
#define LI   1024
#define L    1536
#define QKV3 9216
#define MOD6 18432
#define MSPLIT 16
#define MROWS (H / MSPLIT)

#define ROWB   144
#define ABUF   (128 * ROWB)
#define STAGEB (2 * ABUF)
#define DSMEM  (2 * STAGEB)

// flash-attention smem layout
#define QROWB 272
#define FQ_BYTES (128 * QROWB)
#define FK_BYTES (64 * QROWB)
#define FV_BYTES (128 * ROWB)
#define FSTAGE (FK_BYTES + FV_BYTES)
#define FSMEM (FQ_BYTES + 2 * FSTAGE)   // 106496; x2 CTA = 212992 <= 228KB

// ---------------- scratch ----------------
__device__ float g_mod_img[MOD6];
__device__ float g_mod_txt[MOD6];
__device__ float g_modp[(size_t)2 * MSPLIT * MOD6];
__device__ float g_res2[(size_t)L * H];
__device__ __align__(16) __half g_qkvh[(size_t)L * QKV3];
__device__ __align__(16) __half g_xmod[(size_t)L * H];
__device__ __align__(16) __half g_q   [(size_t)NH * L * HD];
__device__ __align__(16) __half g_k   [(size_t)NH * L * HD];
__device__ __align__(16) __half g_v   [(size_t)NH * HD * L];
__device__ __align__(16) __half g_attn[(size_t)L * H];
__device__ __align__(16) __half g_hbuf[(size_t)L * H];
__device__ __align__(16) __half g_fc1 [(size_t)L * MLPD];
__device__ __align__(16) __half g_qkvw_t [(size_t)QKV3 * H];
__device__ __align__(16) __half g_qkvcw_t[(size_t)QKV3 * H];
__device__ __align__(16) __half g_outw_t [(size_t)H * H];
__device__ __align__(16) __half g_outcw_t[(size_t)H * H];
__device__ __align__(16) __half g_fc1w_t [(size_t)MLPD * H];
__device__ __align__(16) __half g_fc1cw_t[(size_t)MLPD * H];
__device__ __align__(16) __half g_fc2w_t [(size_t)H * MLPD];
__device__ __align__(16) __half g_fc2cw_t[(size_t)H * MLPD];

// ---------------- ptx helpers ----------------
__device__ __forceinline__ uint32_t smem_u32(const void* p) {
    uint32_t a;
    asm("{ .reg .u64 t; cvta.to.shared.u64 t, %1; cvt.u32.u64 %0, t; }" : "=r"(a) : "l"(p));
    return a;
}
__device__ __forceinline__ void cp16(uint32_t dst, const void* src) {
    asm volatile("cp.async.cg.shared.global [%0], [%1], 16;" :: "r"(dst), "l"(src));
}
__device__ __forceinline__ void cp_commit() { asm volatile("cp.async.commit_group;"); }
__device__ __forceinline__ void cp_wait1()  { asm volatile("cp.async.wait_group 1;"); }
__device__ __forceinline__ void ldm4(unsigned* r, uint32_t a) {
    asm volatile("ldmatrix.sync.aligned.m8n8.x4.shared.b16 {%0,%1,%2,%3}, [%4];"
                 : "=r"(r[0]), "=r"(r[1]), "=r"(r[2]), "=r"(r[3]) : "r"(a));
}
__device__ __forceinline__ void mma_f16(float* c, const unsigned* a, const unsigned* b) {
    asm volatile(
        "mma.sync.aligned.m16n8k16.row.col.f32.f16.f16.f32 "
        "{%0,%1,%2,%3}, {%4,%5,%6,%7}, {%8,%9}, {%0,%1,%2,%3};\n"
        : "+f"(c[0]), "+f"(c[1]), "+f"(c[2]), "+f"(c[3])
        : "r"(a[0]), "r"(a[1]), "r"(a[2]), "r"(a[3]), "r"(b[0]), "r"(b[1]));
}
__device__ __forceinline__ float gelu_tanh(float x) {
    return 0.5f * x * (1.f + tanhf(0.7978845608028654f * (x + 0.044715f * x * x * x)));
}
__device__ __forceinline__ unsigned packh2(float lo, float hi) {
    __half2 h = __floats2half2_rn(lo, hi);
    return *reinterpret_cast<unsigned*>(&h);
}

// ---------------- reduce helpers ----------------
__device__ __forceinline__ float block_reduce_sum(float v, float* sh) {
    #pragma unroll
    for (int o = 16; o; o >>= 1) v += __shfl_xor_sync(0xffffffffu, v, o);
    int w = threadIdx.x >> 5;
    if ((threadIdx.x & 31) == 0) sh[w] = v;
    __syncthreads();
    if (threadIdx.x < 32) {
        float x = (threadIdx.x < (blockDim.x >> 5)) ? sh[threadIdx.x] : 0.f;
        #pragma unroll
        for (int o = 16; o; o >>= 1) x += __shfl_xor_sync(0xffffffffu, x, o);
        if (threadIdx.x == 0) sh[0] = x;
    }
    __syncthreads();
    return sh[0];
}

// ---------------- weight convert+transpose (round-10 tile), paired via z ----------------
__global__ void __launch_bounds__(256) wtp_kernel(const float* __restrict__ w1,
                                                  const float* __restrict__ w2,
                                                  __half* __restrict__ o1,
                                                  __half* __restrict__ o2,
                                                  int K, int N) {
    __shared__ float t[64][33];
    const float* W  = blockIdx.z ? w2 : w1;
    __half*      Wt = blockIdx.z ? o2 : o1;
    const int n0 = blockIdx.x * 32;
    const int k0 = blockIdx.y * 64;
    const int tid = threadIdx.x;
    #pragma unroll
    for (int r = 0; r < 2; r++) {
        int idx = tid + r * 256;
        int k = idx >> 3, n4 = (idx & 7) * 4;
        float4 v = *(const float4*)&W[(size_t)(k0 + k) * N + n0 + n4];
        t[k][n4] = v.x; t[k][n4 + 1] = v.y; t[k][n4 + 2] = v.z; t[k][n4 + 3] = v.w;
    }
    __syncthreads();
    int n = tid >> 3, kq = (tid & 7) * 8;
    __half hv[8];
    #pragma unroll
    for (int i = 0; i < 8; i++) hv[i] = __float2half(t[kq + i][n]);
    *(uint4*)&Wt[(size_t)(n0 + n) * K + k0 + kq] = *(uint4*)hv;
}

// ================= fp16 NT GEMM: 128x128 block, 4 warps, 64x64 warp tile =================
__global__ void __launch_bounds__(128, 2) hgemm(const __half* __restrict__ A, int lda, long long sA,
                                                const __half* __restrict__ B, const __half* __restrict__ B2,
                                                int ldb, long long sB,
                                                void* __restrict__ Cv, void* __restrict__ Cv2,
                                                int ldc, long long sC, int c_half,
                                                int K, float alpha, int mSplit,
                                                const float* __restrict__ bias, const float* __restrict__ bias2,
                                                const float* __restrict__ gate, const float* __restrict__ gate2,
                                                const float* __restrict__ residual, const float* __restrict__ residual2,
                                                int ldr, int mode) {
    extern __shared__ char smem[];
    const int tid  = threadIdx.x;
    const int warp = tid >> 5, lane = tid & 31;
    const int g = lane >> 2, tg = lane & 3;
    const int bm = blockIdx.x * 128, bn = blockIdx.y * 128;
    const int wm = (warp >> 1) * 64, wn = (warp & 1) * 64;

    const bool second = (int)blockIdx.x >= mSplit;
    const __half* Bp = second ? B2 : B;
    const float* biasp = second ? bias2 : bias;
    const float* gatep = second ? gate2 : gate;
    const float* resp  = second ? residual2 : residual;
    void* Cp = second ? Cv2 : Cv;

    const __half* Ap = A + (long long)blockIdx.z * sA + (long long)bm * lda;
    Bp += (long long)blockIdx.z * sB + (long long)bn * ldb;

    const uint32_t s0 = smem_u32(smem);
    const int cm = tid >> 3, ckh = tid & 7;

    const uint32_t a_off = (uint32_t)((wm + (lane & 7) + ((lane >> 3) & 1) * 8) * ROWB + (lane >> 4) * 16);
    const uint32_t b_off = (uint32_t)((wn + (lane & 7) + ((lane >> 4) & 1) * 8) * ROWB + ((lane >> 3) & 1) * 16);

    const int nch = K >> 6;

    {
        const uint32_t sa = s0, sb = s0 + ABUF;
        #pragma unroll
        for (int r = 0; r < 8; r++) {
            int m = cm + r * 16;
            cp16(sa + m * ROWB + ckh * 16, Ap + (long long)m * lda + ckh * 8);
            cp16(sb + m * ROWB + ckh * 16, Bp + (long long)m * ldb + ckh * 8);
        }
        cp_commit();
    }

    float acc[4][8][4] = {};
    for (int c = 0; c < nch; c++) {
        const int p = c & 1;
        if (c + 1 < nch) {
            const int q = (c + 1) & 1;
            const int k0 = (c + 1) << 6;
            const uint32_t sa = s0 + q * STAGEB, sb = sa + ABUF;
            #pragma unroll
            for (int r = 0; r < 8; r++) {
                int m = cm + r * 16;
                cp16(sa + m * ROWB + ckh * 16, Ap + (long long)m * lda + k0 + ckh * 8);
                cp16(sb + m * ROWB + ckh * 16, Bp + (long long)m * ldb + k0 + ckh * 8);
            }
        }
        cp_commit();
        cp_wait1();
        __syncthreads();

        const uint32_t ab = s0 + p * STAGEB + a_off;
        const uint32_t bb = s0 + p * STAGEB + ABUF + b_off;
        #pragma unroll
        for (int ks = 0; ks < 4; ks++) {
            unsigned af[4][4], bf[8][2];
            #pragma unroll
            for (int i = 0; i < 4; i++)
                ldm4(af[i], ab + i * (16 * ROWB) + ks * 32);
            #pragma unroll
            for (int jp = 0; jp < 4; jp++) {
                unsigned t4[4];
                ldm4(t4, bb + jp * (16 * ROWB) + ks * 32);
                bf[jp * 2][0] = t4[0]; bf[jp * 2][1] = t4[1];
                bf[jp * 2 + 1][0] = t4[2]; bf[jp * 2 + 1][1] = t4[3];
            }
            #pragma unroll
            for (int i = 0; i < 4; i++)
                #pragma unroll
                for (int j = 0; j < 8; j++)
                    mma_f16(acc[i][j], af[i], bf[j]);
        }
        __syncthreads();
    }

    #pragma unroll
    for (int i = 0; i < 4; i++) {
        int r0 = bm + wm + i * 16 + g;
        #pragma unroll
        for (int j = 0; j < 8; j++) {
            int cc = bn + wn + j * 8 + 2 * tg;
            float v0 = acc[i][j][0] * alpha, v1 = acc[i][j][1] * alpha;
            float v2 = acc[i][j][2] * alpha, v3 = acc[i][j][3] * alpha;
            if (biasp) {
                float b0 = biasp[cc], b1 = biasp[cc + 1];
                v0 += b0; v1 += b1; v2 += b0; v3 += b1;
            }
            if (mode == 1) {
                v0 = gelu_tanh(v0); v1 = gelu_tanh(v1);
                v2 = gelu_tanh(v2); v3 = gelu_tanh(v3);
            } else if (mode == 2) {
                const float* q0 = resp + (long long)r0 * ldr + cc;
                const float* q1 = resp + (long long)(r0 + 8) * ldr + cc;
                float g0 = gatep[cc], g1 = gatep[cc + 1];
                v0 = q0[0] + g0 * v0; v1 = q0[1] + g1 * v1;
                v2 = q1[0] + g0 * v2; v3 = q1[1] + g1 * v3;
            }
            if (c_half) {
                __half* C = (__half*)Cp + (long long)blockIdx.z * sC;
                *(__half2*)&C[(long long)r0 * ldc + cc]       = __floats2half2_rn(v0, v1);
                *(__half2*)&C[(long long)(r0 + 8) * ldc + cc] = __floats2half2_rn(v2, v3);
            } else {
                float* C = (float*)Cp + (long long)blockIdx.z * sC;
                float2 o0 = {v0, v1}, o1 = {v2, v3};
                *(float2*)&C[(long long)r0 * ldc + cc]       = o0;
                *(float2*)&C[(long long)(r0 + 8) * ldc + cc] = o1;
            }
        }
    }
}

// ================= fused flash attention (2 CTAs/SM) =================
__global__ void __launch_bounds__(256, 2) fattn(const __half* __restrict__ gq,
                                                const __half* __restrict__ gk,
                                                const __half* __restrict__ gv,
                                                __half* __restrict__ attnb) {
    extern __shared__ char smem[];
    const int tid  = threadIdx.x;
    const int warp = tid >> 5, lane = tid & 31;
    const int g = lane >> 2, tg = lane & 3;
    const int bm = blockIdx.x * 128;
    const int h  = blockIdx.y;
    const float alpha = 0.08838834764831845f;

    const __half* Qg = gq + ((size_t)h * L + bm) * HD;
    const __half* Kg = gk + (size_t)h * L * HD;
    const __half* Vg = gv + (size_t)h * HD * L;

    const uint32_t s0 = smem_u32(smem);
    const uint32_t sq = s0;

    #pragma unroll
    for (int r = 0; r < 8; r++) {
        int id = tid + r * 256;
        int row = id >> 4, ch = id & 15;
        cp16(sq + row * QROWB + ch * 16, Qg + (size_t)row * HD + ch * 8);
    }
    {
        const uint32_t sk = s0 + FQ_BYTES, sv = sk + FK_BYTES;
        #pragma unroll
        for (int r = 0; r < 4; r++) {
            int id = tid + r * 256;
            int row = id >> 4, ch = id & 15;
            cp16(sk + row * QROWB + ch * 16, Kg + (size_t)row * HD + ch * 8);
        }
        #pragma unroll
        for (int r = 0; r < 4; r++) {
            int id = tid + r * 256;
            int row = id >> 3, ch = id & 7;
            cp16(sv + row * ROWB + ch * 16, Vg + (size_t)row * L + ch * 8);
        }
        cp_commit();
    }

    const uint32_t a_off  = (uint32_t)((warp * 16 + (lane & 7) + ((lane >> 3) & 1) * 8) * QROWB + (lane >> 4) * 16);
    const uint32_t bk_off = (uint32_t)(((lane & 7) + ((lane >> 4) & 1) * 8) * QROWB + ((lane >> 3) & 1) * 16);
    const uint32_t bv_off = (uint32_t)(((lane & 7) + ((lane >> 4) & 1) * 8) * ROWB  + ((lane >> 3) & 1) * 16);

    float o_acc[16][4] = {};
    float m0 = -3.0e38f, m1 = -3.0e38f;
    float l0 = 0.f, l1 = 0.f;

    const int NCH = L / 64;
    for (int c = 0; c < NCH; c++) {
        const int p = c & 1;
        if (c + 1 < NCH) {
            const int q = (c + 1) & 1;
            const int n0 = (c + 1) * 64;
            const uint32_t sk = s0 + FQ_BYTES + q * FSTAGE, sv = sk + FK_BYTES;
            #pragma unroll
            for (int r = 0; r < 4; r++) {
                int id = tid + r * 256;
                int row = id >> 4, ch = id & 15;
                cp16(sk + row * QROWB + ch * 16, Kg + (size_t)(n0 + row) * HD + ch * 8);
            }
            #pragma unroll
            for (int r = 0; r < 4; r++) {
                int id = tid + r * 256;
                int row = id >> 3, ch = id & 7;
                cp16(sv + row * ROWB + ch * 16, Vg + (size_t)row * L + n0 + ch * 8);
            }
        }
        cp_commit();
        cp_wait1();
        __syncthreads();

        const uint32_t skb = s0 + FQ_BYTES + p * FSTAGE;
        const uint32_t svb = skb + FK_BYTES;

        // ---- S = alpha * Q K^T ----
        float sacc[8][4] = {};
        #pragma unroll
        for (int ks = 0; ks < 8; ks++) {
            unsigned af[4];
            ldm4(af, sq + a_off + ks * 32);
            #pragma unroll
            for (int jp = 0; jp < 4; jp++) {
                unsigned t4[4];
                ldm4(t4, skb + bk_off + jp * (16 * QROWB) + ks * 32);
                mma_f16(sacc[jp * 2],     af, t4);
                mma_f16(sacc[jp * 2 + 1], af, t4 + 2);
            }
        }

        // ---- online softmax ----
        float cm0 = -3.0e38f, cm1 = -3.0e38f;
        #pragma unroll
        for (int j = 0; j < 8; j++) {
            sacc[j][0] *= alpha; sacc[j][1] *= alpha;
            sacc[j][2] *= alpha; sacc[j][3] *= alpha;
            cm0 = fmaxf(cm0, fmaxf(sacc[j][0], sacc[j][1]));
            cm1 = fmaxf(cm1, fmaxf(sacc[j][2], sacc[j][3]));
        }
        cm0 = fmaxf(cm0, __shfl_xor_sync(0xffffffffu, cm0, 1));
        cm0 = fmaxf(cm0, __shfl_xor_sync(0xffffffffu, cm0, 2));
        cm1 = fmaxf(cm1, __shfl_xor_sync(0xffffffffu, cm1, 1));
        cm1 = fmaxf(cm1, __shfl_xor_sync(0xffffffffu, cm1, 2));
        const float mn0 = fmaxf(m0, cm0), mn1 = fmaxf(m1, cm1);
        const float sc0 = __expf(m0 - mn0), sc1 = __expf(m1 - mn1);
        m0 = mn0; m1 = mn1;

        float rs0 = 0.f, rs1 = 0.f;
        #pragma unroll
        for (int j = 0; j < 8; j++) {
            sacc[j][0] = __expf(sacc[j][0] - mn0);
            sacc[j][1] = __expf(sacc[j][1] - mn0);
            sacc[j][2] = __expf(sacc[j][2] - mn1);
            sacc[j][3] = __expf(sacc[j][3] - mn1);
            rs0 += sacc[j][0] + sacc[j][1];
            rs1 += sacc[j][2] + sacc[j][3];
        }
        rs0 += __shfl_xor_sync(0xffffffffu, rs0, 1);
        rs0 += __shfl_xor_sync(0xffffffffu, rs0, 2);
        rs1 += __shfl_xor_sync(0xffffffffu, rs1, 1);
        rs1 += __shfl_xor_sync(0xffffffffu, rs1, 2);
        l0 = l0 * sc0 + rs0;
        l1 = l1 * sc1 + rs1;
        #pragma unroll
        for (int j = 0; j < 16; j++) {
            o_acc[j][0] *= sc0; o_acc[j][1] *= sc0;
            o_acc[j][2] *= sc1; o_acc[j][3] *= sc1;
        }

        // ---- O += P V, pf packed per kk, bf in 8-wide halves ----
        #pragma unroll
        for (int kk = 0; kk < 4; kk++) {
            unsigned pf[4];
            pf[0] = packh2(sacc[2*kk][0],   sacc[2*kk][1]);
            pf[1] = packh2(sacc[2*kk][2],   sacc[2*kk][3]);
            pf[2] = packh2(sacc[2*kk+1][0], sacc[2*kk+1][1]);
            pf[3] = packh2(sacc[2*kk+1][2], sacc[2*kk+1][3]);
            #pragma unroll
            for (int half = 0; half < 2; half++) {
                unsigned bf[8][2];
                #pragma unroll
                for (int jp = 0; jp < 4; jp++) {
                    unsigned t4[4];
                    ldm4(t4, svb + bv_off + (half * 4 + jp) * (16 * ROWB) + kk * 32);
                    bf[jp * 2][0] = t4[0]; bf[jp * 2][1] = t4[1];
                    bf[jp * 2 + 1][0] = t4[2]; bf[jp * 2 + 1][1] = t4[3];
                }
                #pragma unroll
                for (int j = 0; j < 8; j++)
                    mma_f16(o_acc[half * 8 + j], pf, bf[j]);
            }
        }
        __syncthreads();
    }

    // ---- epilogue ----
    const float inv0 = 1.f / l0, inv1 = 1.f / l1;
    const int row0 = bm + warp * 16 + g;
    __half* d0 = attnb + (size_t)row0 * H + h * HD;
    __half* d1 = attnb + (size_t)(row0 + 8) * H + h * HD;
    #pragma unroll
    for (int j = 0; j < 16; j++) {
        int cc = j * 8 + 2 * tg;
        *(__half2*)&d0[cc] = __floats2half2_rn(o_acc[j][0] * inv0, o_acc[j][1] * inv0);
        *(__half2*)&d1[cc] = __floats2half2_rn(o_acc[j][2] * inv1, o_acc[j][3] * inv1);
    }
}

// ---------------- modulation GEMV: split-K partials ----------------
__global__ void __launch_bounds__(256) mod_split(const float* __restrict__ vec,
                                                 const float* __restrict__ w1,
                                                 const float* __restrict__ w2,
                                                 float* __restrict__ partial) {
    __shared__ float sv[MROWS];
    const float* w = blockIdx.z ? w2 : w1;
    const int i0 = blockIdx.y * MROWS;
    if (threadIdx.x < MROWS) {
        float x = vec[i0 + threadIdx.x];
        sv[threadIdx.x] = x / (1.f + expf(-x));
    }
    __syncthreads();
    const int col = blockIdx.x * 256 + threadIdx.x;
    float acc = 0.f;
    const float* wp = w + (size_t)i0 * MOD6 + col;
    #pragma unroll 8
    for (int i = 0; i < MROWS; i++) acc += sv[i] * wp[(size_t)i * MOD6];
    partial[((size_t)blockIdx.z * MSPLIT + blockIdx.y) * MOD6 + col] = acc;
}

__global__ void __launch_bounds__(256) mod_reduce(const float* __restrict__ partial,
                                                  const float* __restrict__ b1,
                                                  const float* __restrict__ b2,
                                                  float* __restrict__ o1,
                                                  float* __restrict__ o2) {
    const int col = blockIdx.x * 256 + threadIdx.x;
    const int z = blockIdx.y;
    const float* p = partial + (size_t)z * MSPLIT * MOD6 + col;
    float acc = (z ? b2 : b1)[col];
    #pragma unroll
    for (int k = 0; k < MSPLIT; k++) acc += p[(size_t)k * MOD6];
    (z ? o2 : o1)[col] = acc;
}

// ---------------- LayerNorm + modulate (dual-region) -> half ----------------
__global__ void __launch_bounds__(256) ln_mod_kernel(const float* __restrict__ x1,
                                                     const float* __restrict__ x2,
                                                     int split,
                                                     __half* __restrict__ y,
                                                     const float* __restrict__ sh1,
                                                     const float* __restrict__ sc1,
                                                     const float* __restrict__ sh2,
                                                     const float* __restrict__ sc2) {
    __shared__ float s0[32], s1[32];
    int row = blockIdx.x;
    const bool sec = row >= split;
    const float* xr = (sec ? x2 : x1) + (size_t)row * H;
    const float* sh = sec ? sh2 : sh1;
    const float* sc = sec ? sc2 : sc1;
    float s = 0.f, s2 = 0.f;
    for (int j = threadIdx.x; j < H; j += 256) {
        float v = xr[j];
        s += v; s2 += v * v;
    }
    float sum  = block_reduce_sum(s,  s0);
    float sum2 = block_reduce_sum(s2, s1);
    float mean = sum * (1.f / H);
    float var  = sum2 * (1.f / H) - mean * mean;
    float inv  = rsqrtf(var + 1e-6f);
    __half* yr = y + (size_t)row * H;
    for (int j = threadIdx.x * 2; j < H; j += 512) {
        float a = (xr[j]     - mean) * inv * (1.f + sc[j])     + sh[j];
        float b = (xr[j + 1] - mean) * inv * (1.f + sc[j + 1]) + sh[j + 1];
        *(__half2*)&yr[j] = __floats2half2_rn(a, b);
    }
}

// ---------------- QKV postprocess ----------------
__global__ void __launch_bounds__(256) qkv_post_kernel(const __half* __restrict__ qkv,
                                                       const float* __restrict__ pe,
                                                       const float* __restrict__ nq_i,
                                                       const float* __restrict__ nk_i,
                                                       const float* __restrict__ nq_t,
                                                       const float* __restrict__ nk_t,
                                                       __half* __restrict__ gq,
                                                       __half* __restrict__ gk,
                                                       __half* __restrict__ gv) {
    __shared__ __half vt[128][34];
    const int h = blockIdx.y;
    const int s0 = blockIdx.x * 32;
    const int warp = threadIdx.x >> 5, lane = threadIdx.x & 31;
    const int d0 = lane * 4;

    #pragma unroll
    for (int ti = 0; ti < 4; ti++) {
        const int s = s0 + warp * 4 + ti;
        const __half* base = qkv + (size_t)s * QKV3 + h * HD + d0;
        uint2 qu = *(const uint2*)base;
        uint2 ku = *(const uint2*)(base + H);
        uint2 vu = *(const uint2*)(base + 2 * H);
        __half2 qh0 = *(__half2*)&qu.x, qh1 = *(__half2*)&qu.y;
        __half2 kh0 = *(__half2*)&ku.x, kh1 = *(__half2*)&ku.y;
        float q[4] = {__low2float(qh0), __high2float(qh0), __low2float(qh1), __high2float(qh1)};
        float k[4] = {__low2float(kh0), __high2float(kh0), __low2float(kh1), __high2float(kh1)};
        float sq = q[0]*q[0] + q[1]*q[1] + q[2]*q[2] + q[3]*q[3];
        float sk = k[0]*k[0] + k[1]*k[1] + k[2]*k[2] + k[3]*k[3];
        #pragma unroll
        for (int o = 16; o; o >>= 1) {
            sq += __shfl_xor_sync(0xffffffffu, sq, o);
            sk += __shfl_xor_sync(0xffffffffu, sk, o);
        }
        const float rq = rsqrtf(sq * (1.f / HD) + 1e-6f);
        const float rk = rsqrtf(sk * (1.f / HD) + 1e-6f);
        const bool is_txt = s < LT;
        const float* nq = is_txt ? nq_t : nq_i;
        const float* nk = is_txt ? nk_t : nk_i;
        float qn[4], kn[4];
        #pragma unroll
        for (int e = 0; e < 4; e++) {
            qn[e] = q[e] * rq * nq[d0 + e];
            kn[e] = k[e] * rk * nk[d0 + e];
        }
        const float4 f0 = *(const float4*)(pe + ((size_t)s * 64 + lane * 2) * 4);
        const float4 f1 = *(const float4*)(pe + ((size_t)s * 64 + lane * 2 + 1) * 4);
        float qo[4], ko[4];
        qo[0] = f0.x * qn[0] + f0.y * qn[1]; qo[1] = f0.z * qn[0] + f0.w * qn[1];
        qo[2] = f1.x * qn[2] + f1.y * qn[3]; qo[3] = f1.z * qn[2] + f1.w * qn[3];
        ko[0] = f0.x * kn[0] + f0.y * kn[1]; ko[1] = f0.z * kn[0] + f0.w * kn[1];
        ko[2] = f1.x * kn[2] + f1.y * kn[3]; ko[3] = f1.z * kn[2] + f1.w * kn[3];
        __half2 qw0 = __floats2half2_rn(qo[0], qo[1]), qw1 = __floats2half2_rn(qo[2], qo[3]);
        __half2 kw0 = __floats2half2_rn(ko[0], ko[1]), kw1 = __floats2half2_rn(ko[2], ko[3]);
        const size_t idx = ((size_t)h * L + s) * HD + d0;
        uint2 qst = {*(unsigned*)&qw0, *(unsigned*)&qw1};
        uint2 kst = {*(unsigned*)&kw0, *(unsigned*)&kw1};
        *(uint2*)&gq[idx] = qst;
        *(uint2*)&gk[idx] = kst;
        __half2 vh0 = *(__half2*)&vu.x, vh1 = *(__half2*)&vu.y;
        const int tcol = warp * 4 + ti;
        vt[d0 + 0][tcol] = __low2half(vh0);
        vt[d0 + 1][tcol] = __high2half(vh0);
        vt[d0 + 2][tcol] = __low2half(vh1);
        vt[d0 + 3][tcol] = __high2half(vh1);
    }
    __syncthreads();
    const int d = threadIdx.x >> 1, hf = (threadIdx.x & 1) * 16;
    __half tmp[16];
    #pragma unroll
    for (int i = 0; i < 16; i++) tmp[i] = vt[d][hf + i];
    __half* dst = gv + ((size_t)h * HD + d) * L + s0 + hf;
    *(uint4*)dst       = *(uint4*)tmp;
    *(uint4*)(dst + 8) = *(uint4*)(tmp + 8);
}

// ---------------- launch ----------------
extern "C" void kernel_launch(void* const* d_in, const int* in_sizes, int n_in,
                              void* d_out, int out_size) {
    const float* img      = (const float*)d_in[0];
    const float* txt      = (const float*)d_in[1];
    const float* vec      = (const float*)d_in[2];
    const float* pe       = (const float*)d_in[3];
    const float* mod_w    = (const float*)d_in[4];
    const float* mod_b    = (const float*)d_in[5];
    const float* qkv_w    = (const float*)d_in[6];
    const float* qkv_b    = (const float*)d_in[7];
    const float* norm_q_w = (const float*)d_in[8];
    const float* norm_k_w = (const float*)d_in[9];
    const float* out_w    = (const float*)d_in[10];
    const float* out_b    = (const float*)d_in[11];
    const float* fc1_w    = (const float*)d_in[12];
    const float* fc1_b    = (const float*)d_in[13];
    const float* fc2_w    = (const float*)d_in[14];
    const float* fc2_b    = (const float*)d_in[15];
    const float* mod_c_w  = (const float*)d_in[16];
    const float* mod_c_b  = (const float*)d_in[17];
    const float* qkv_c_w  = (const float*)d_in[18];
    const float* qkv_c_b  = (const float*)d_in[19];
    const float* norm_aq_w= (const float*)d_in[20];
    const float* norm_ak_w= (const float*)d_in[21];
    const float* out_c_w  = (const float*)d_in[22];
    const float* out_c_b  = (const float*)d_in[23];
    const float* fc1_c_w  = (const float*)d_in[24];
    const float* fc1_c_b  = (const float*)d_in[25];
    const float* fc2_c_w  = (const float*)d_in[26];
    const float* fc2_c_b  = (const float*)d_in[27];
    float* out = (float*)d_out;

    float *modi, *modt, *modp, *res2;
    __half *qkvh, *xmod, *qb, *kb, *vb, *attnb, *hb, *fc1b;
    __half *qkvw_t, *qkvcw_t, *outw_t, *outcw_t, *fc1w_t, *fc1cw_t, *fc2w_t, *fc2cw_t;
    cudaGetSymbolAddress((void**)&modi,   g_mod_img);
    cudaGetSymbolAddress((void**)&modt,   g_mod_txt);
    cudaGetSymbolAddress((void**)&modp,   g_modp);
    cudaGetSymbolAddress((void**)&res2,   g_res2);
    cudaGetSymbolAddress((void**)&qkvh,   g_qkvh);
    cudaGetSymbolAddress((void**)&xmod,   g_xmod);
    cudaGetSymbolAddress((void**)&qb,     g_q);
    cudaGetSymbolAddress((void**)&kb,     g_k);
    cudaGetSymbolAddress((void**)&vb,     g_v);
    cudaGetSymbolAddress((void**)&attnb,  g_attn);
    cudaGetSymbolAddress((void**)&hb,     g_hbuf);
    cudaGetSymbolAddress((void**)&fc1b,   g_fc1);
    cudaGetSymbolAddress((void**)&qkvw_t, g_qkvw_t);
    cudaGetSymbolAddress((void**)&qkvcw_t,g_qkvcw_t);
    cudaGetSymbolAddress((void**)&outw_t, g_outw_t);
    cudaGetSymbolAddress((void**)&outcw_t,g_outcw_t);
    cudaGetSymbolAddress((void**)&fc1w_t, g_fc1w_t);
    cudaGetSymbolAddress((void**)&fc1cw_t,g_fc1cw_t);
    cudaGetSymbolAddress((void**)&fc2w_t, g_fc2w_t);
    cudaGetSymbolAddress((void**)&fc2cw_t,g_fc2cw_t);

    cudaFuncSetAttribute(hgemm, cudaFuncAttributeMaxDynamicSharedMemorySize, DSMEM);
    cudaFuncSetAttribute(fattn, cudaFuncAttributeMaxDynamicSharedMemorySize, FSMEM);

    const float* img_off = img - (size_t)LT * H;
    float* out_img_off = out - (size_t)LT * H;
    float* out_txt     = out + (size_t)LI * H;

    // qkv weights (paired), modulation, ln, qkv GEMM
    wtp_kernel<<<dim3(QKV3/32, H/64, 2), 256>>>(qkv_c_w, qkv_w, qkvcw_t, qkvw_t, H, QKV3);
    mod_split<<<dim3(MOD6/256, MSPLIT, 2), 256>>>(vec, mod_w, mod_c_w, modp);
    mod_reduce<<<dim3(MOD6/256, 2), 256>>>(modp, mod_b, mod_c_b, modi, modt);
    ln_mod_kernel<<<L, 256>>>(txt, img_off, LT, xmod,
                              modt, modt + H, modi, modi + H);

    hgemm<<<dim3(L/128, QKV3/128, 1), 128, DSMEM>>>(
        xmod, H, 0, qkvcw_t, qkvw_t, H, 0,
        qkvh, qkvh, QKV3, 0, 1, H, 1.f, LT/128,
        qkv_c_b, qkv_b, nullptr, nullptr, nullptr, nullptr, 0, 0);

    // remaining weights (paired)
    wtp_kernel<<<dim3(H/32,    H/64, 2), 256>>>(out_c_w, out_w, outcw_t, outw_t, H, H);
    wtp_kernel<<<dim3(MLPD/32, H/64, 2), 256>>>(fc1_c_w, fc1_w, fc1cw_t, fc1w_t, H, MLPD);
    wtp_kernel<<<dim3(H/32, MLPD/64, 2), 256>>>(fc2_c_w, fc2_w, fc2cw_t, fc2w_t, MLPD, H);

    {
        dim3 g(L / 32, NH);
        qkv_post_kernel<<<g, 256>>>(qkvh, pe, norm_q_w, norm_k_w, norm_aq_w, norm_ak_w,
                                    qb, kb, vb);
    }

    // fused flash attention
    fattn<<<dim3(L/128, NH), 256, FSMEM>>>(qb, kb, vb, attnb);

    // out projection + gated residual (merged)
    hgemm<<<dim3(L/128, H/128, 1), 128, DSMEM>>>(
        attnb, H, 0, outcw_t, outw_t, H, 0,
        res2, res2, H, 0, 0, H, 1.f, LT/128,
        out_c_b, out_b, modt + 2 * H, modi + 2 * H, txt, img_off, H, 2);

    // LN + modulate stage 2 (merged)
    ln_mod_kernel<<<L, 256>>>(res2, res2, LT, hb,
                              modt + 3 * H, modt + 4 * H, modi + 3 * H, modi + 4 * H);

    // fc1 + gelu (merged)
    hgemm<<<dim3(L/128, MLPD/128, 1), 128, DSMEM>>>(
        hb, H, 0, fc1cw_t, fc1w_t, H, 0,
        fc1b, fc1b, MLPD, 0, 1, H, 1.f, LT/128,
        fc1_c_b, fc1_b, nullptr, nullptr, nullptr, nullptr, 0, 1);

    // fc2 + gated residual (merged) -> final output
    hgemm<<<dim3(L/128, H/128, 1), 128, DSMEM>>>(
        fc1b, MLPD, 0, fc2cw_t, fc2w_t, MLPD, 0,
        out_txt, out_img_off, H, 0, 0, MLPD, 1.f, LT/128,
        fc2_c_b, fc2_b, modt + 5 * H, modi + 5 * H, res2, res2, H, 2);

    (void)in_sizes; (void)n_in; (void)out_size;
}